// round 5
// baseline (speedup 1.0000x reference)
#include <cuda_runtime.h>
#include <cstdint>

// ---------------- problem constants ----------------
#define EE      500000
#define NN      100000
#define NTEXT   90000
#define EMBD    256
#define NRELC   500
#define KE      266      // h_e feature width
#define KP      272      // padded to /16
#define NSAMP   5
#define PREDIN  1044
#define W1FLAT  267264   // 256*1044
#define CAB     2560     // 5 samples * (256 A + 256 B)

// ---------------- device scratch (static, allowed) ----------------
__device__ float g_ext[(size_t)NN * KP];        // node features, padded
__device__ float g_AB[(size_t)NN * CAB];        // per-node per-sample A|B  (1.02 GB)
__device__ float g_w1s[(size_t)NSAMP * W1FLAT]; // sampled w1 (flat per sample)
__device__ float g_b1s[NSAMP * 256];
__device__ float g_w2s[NSAMP * 256];
__device__ float g_b2s[NSAMP];
__device__ float g_cvec[NSAMP * 256];           // q@Wq^T + b1
__device__ float g_Rc[(size_t)NSAMP * NRELC * 256];
__device__ float g_Wcat[(size_t)CAB * KP];      // GEMM B matrix (row-major, K-contig)
__device__ float g_sumA[NN * 2];
__device__ float g_sumB[NN * 2];
__device__ float g_degT[NN];
__device__ float g_degH[NN];
__device__ float g_b2sum_buf[1];

struct Keys { unsigned int k[NSAMP][4][2]; };

// ---------------- threefry2x32 (JAX-exact) ----------------
__host__ __device__ __forceinline__ unsigned int rotl32(unsigned int x, int r) {
    return (x << r) | (x >> (32 - r));
}
__host__ __device__ __forceinline__ void tf2x32(unsigned int k0, unsigned int k1,
                                                unsigned int x0, unsigned int x1,
                                                unsigned int& o0, unsigned int& o1) {
    unsigned int ks2 = k0 ^ k1 ^ 0x1BD11BDAu;
    x0 += k0; x1 += k1;
#define TFR(r) { x0 += x1; x1 = rotl32(x1, r); x1 ^= x0; }
    TFR(13) TFR(15) TFR(26) TFR(6)   x0 += k1;  x1 += ks2 + 1u;
    TFR(17) TFR(29) TFR(16) TFR(24)  x0 += ks2; x1 += k0 + 2u;
    TFR(13) TFR(15) TFR(26) TFR(6)   x0 += k0;  x1 += k1 + 3u;
    TFR(17) TFR(29) TFR(16) TFR(24)  x0 += k1;  x1 += ks2 + 4u;
    TFR(13) TFR(15) TFR(26) TFR(6)   x0 += ks2; x1 += k0 + 5u;
#undef TFR
    o0 = x0; o1 = x1;
}

// XLA f32 ErfInv (Giles polynomial) — matches jax.lax.erf_inv on f32
__device__ __forceinline__ float erfinv_f32(float x) {
    float w = -log1pf(-x * x);
    float p;
    if (w < 5.0f) {
        w -= 2.5f;
        p = 2.81022636e-08f;
        p = fmaf(p, w, 3.43273939e-07f);
        p = fmaf(p, w, -3.5233877e-06f);
        p = fmaf(p, w, -4.39150654e-06f);
        p = fmaf(p, w, 0.00021858087f);
        p = fmaf(p, w, -0.00125372503f);
        p = fmaf(p, w, -0.00417768164f);
        p = fmaf(p, w, 0.246640727f);
        p = fmaf(p, w, 1.50140941f);
    } else {
        w = sqrtf(w) - 3.0f;
        p = -0.000200214257f;
        p = fmaf(p, w, 0.000100950558f);
        p = fmaf(p, w, 0.00134934322f);
        p = fmaf(p, w, -0.00367342844f);
        p = fmaf(p, w, 0.00573950773f);
        p = fmaf(p, w, -0.0076224613f);
        p = fmaf(p, w, 0.00943887047f);
        p = fmaf(p, w, 1.00167406f);
        p = fmaf(p, w, 2.83297682f);
    }
    return p * x;
}

// jax.random.normal bit path: bits -> [1,2) -> [0,1) -> [-0.99999994, 1) -> sqrt2*erfinv
__device__ __forceinline__ float bits_to_normal(unsigned int b) {
    float f01 = __uint_as_float((b >> 9) | 0x3f800000u) - 1.0f;
    float u = __fadd_rn(__fmul_rn(f01, 2.0f), -0.99999994f);
    u = fmaxf(-0.99999994f, u);
    return __fmul_rn(1.41421356237f, erfinv_f32(u));
}

// jax.nn.softplus = logaddexp(x, 0)
__device__ __forceinline__ float softplusf(float x) {
    return fmaxf(x, 0.0f) + log1pf(expf(-fabsf(x)));
}

// ---------------- kernels ----------------
__global__ void k_zero() {
    int i = blockIdx.x * blockDim.x + threadIdx.x;
    if (i < NN * 2) { g_sumA[i] = 0.0f; g_sumB[i] = 0.0f; }
    if (i < NN)     { g_degT[i] = 0.0f; g_degH[i] = 0.0f; }
}

__global__ void k_scat1(const int* __restrict__ h_id, const int* __restrict__ t_id,
                        const float* __restrict__ topic) {
    int e = blockIdx.x * blockDim.x + threadIdx.x;
    if (e >= EE) return;
    int h = h_id[e], t = t_id[e];
    float x0 = topic[h * 2], x1 = topic[h * 2 + 1];
    atomicAdd(&g_sumA[t * 2], x0); atomicAdd(&g_sumA[t * 2 + 1], x1);
    float y0 = topic[t * 2], y1 = topic[t * 2 + 1];
    atomicAdd(&g_sumB[h * 2], y0); atomicAdd(&g_sumB[h * 2 + 1], y1);
    atomicAdd(&g_degT[t], 1.0f);
    atomicAdd(&g_degH[h], 1.0f);
}

// fill ext cols 0:260 + 262:264, zero the rest; reset sum buffers for pass 2
__global__ void k_build1(const float* __restrict__ ent, const float* __restrict__ nontext,
                         const float* __restrict__ topic) {
    long long idx = (long long)blockIdx.x * blockDim.x + threadIdx.x;
    if (idx >= (long long)NN * KP) return;
    int n = (int)(idx / KP), c = (int)(idx % KP);
    float v = 0.0f;
    if (c < 256) {
        v = (n < NTEXT) ? ent[(size_t)n * 256 + c] : nontext[c];
    } else if (c < 258) {
        v = topic[n * 2 + (c - 256)];
    } else if (c < 260) {
        int k = c - 258;
        v = g_sumA[n * 2 + k] / fmaxf(g_degT[n], 1.0f);
        g_sumA[n * 2 + k] = 0.0f;
    } else if (c >= 262 && c < 264) {
        int k = c - 262;
        v = g_sumB[n * 2 + k] / fmaxf(g_degH[n], 1.0f);
        g_sumB[n * 2 + k] = 0.0f;
    }
    g_ext[(size_t)n * KP + c] = v;
}

__global__ void k_scat2(const int* __restrict__ h_id, const int* __restrict__ t_id) {
    int e = blockIdx.x * blockDim.x + threadIdx.x;
    if (e >= EE) return;
    int h = h_id[e], t = t_id[e];
    float a0 = g_ext[(size_t)h * KP + 258], a1 = g_ext[(size_t)h * KP + 259];
    atomicAdd(&g_sumA[t * 2], a0); atomicAdd(&g_sumA[t * 2 + 1], a1);
    float b0 = g_ext[(size_t)t * KP + 262], b1v = g_ext[(size_t)t * KP + 263];
    atomicAdd(&g_sumB[h * 2], b0); atomicAdd(&g_sumB[h * 2 + 1], b1v);
}

__global__ void k_fill2() {
    int idx = blockIdx.x * blockDim.x + threadIdx.x;
    if (idx >= NN * 2) return;
    int n = idx >> 1, k = idx & 1;
    g_ext[(size_t)n * KP + 260 + k] = g_sumA[n * 2 + k] / fmaxf(g_degT[n], 1.0f);
    g_ext[(size_t)n * KP + 264 + k] = g_sumB[n * 2 + k] / fmaxf(g_degH[n], 1.0f);
}

// PARTITIONABLE threefry (JAX >= 0.4.30 default):
// random_bits(key, 32, shape)[m] = o0 ^ o1 of enc(key, (0, m)) for m < 2^32
__global__ void k_sample(Keys K,
                         const float* __restrict__ w1mu, const float* __restrict__ w1rho,
                         const float* __restrict__ b1mu, const float* __restrict__ b1rho,
                         const float* __restrict__ w2mu, const float* __restrict__ w2rho,
                         const float* __restrict__ b2mu, const float* __restrict__ b2rho) {
    int i = blockIdx.y;
    int j = blockIdx.x * blockDim.x + threadIdx.x;
    unsigned int v0, v1;
    if (j < W1FLAT) {
        tf2x32(K.k[i][0][0], K.k[i][0][1], 0u, (unsigned)j, v0, v1);
        float z = bits_to_normal(v0 ^ v1);
        g_w1s[(size_t)i * W1FLAT + j] = w1mu[j] + z * softplusf(w1rho[j]);
    } else if (j < W1FLAT + 256) {
        int jj = j - W1FLAT;
        tf2x32(K.k[i][1][0], K.k[i][1][1], 0u, (unsigned)jj, v0, v1);
        g_b1s[i * 256 + jj] = b1mu[jj] + bits_to_normal(v0 ^ v1) * softplusf(b1rho[jj]);
    } else if (j < W1FLAT + 512) {
        int jj = j - W1FLAT - 256;
        tf2x32(K.k[i][2][0], K.k[i][2][1], 0u, (unsigned)jj, v0, v1);
        g_w2s[i * 256 + jj] = w2mu[jj] + bits_to_normal(v0 ^ v1) * softplusf(w2rho[jj]);
    } else if (j == W1FLAT + 512) {
        tf2x32(K.k[i][3][0], K.k[i][3][1], 0u, 0u, v0, v1);
        g_b2s[i] = b2mu[0] + bits_to_normal(v0 ^ v1) * softplusf(b2rho[0]);
    }
}

// Wcat[row=i*512+jj][c] : jj<256 -> w1 cols 256+c (h part); jj>=256 -> cols 778+c (t part)
__global__ void k_build_wcat() {
    long long idx = (long long)blockIdx.x * blockDim.x + threadIdx.x;
    if (idx >= (long long)CAB * KP) return;
    int n = (int)(idx / KP), c = (int)(idx % KP);
    float v = 0.0f;
    if (c < KE) {
        int i = n >> 9, jj = n & 511;
        int row = (jj < 256) ? jj : (jj - 256);
        int off = (jj < 256) ? 256 : 778;
        v = g_w1s[((size_t)i * 256 + row) * PREDIN + off + c];
    }
    g_Wcat[idx] = v;
}

__global__ void k_cvec(const float* __restrict__ q) {
    int gw = (blockIdx.x * blockDim.x + threadIdx.x) >> 5;
    int lane = threadIdx.x & 31;
    if (gw >= NSAMP * 256) return;
    int i = gw >> 8, j = gw & 255;
    const float* wrow = &g_w1s[((size_t)i * 256 + j) * PREDIN];
    float s = 0.0f;
    for (int c = lane; c < 256; c += 32) s += q[c] * wrow[c];
    for (int o = 16; o; o >>= 1) s += __shfl_down_sync(0xffffffffu, s, o);
    if (lane == 0) g_cvec[i * 256 + j] = s + g_b1s[i * 256 + j];
}

__global__ void k_rc(const float* __restrict__ rel) {
    int gw = (blockIdx.x * blockDim.x + threadIdx.x) >> 5;
    int lane = threadIdx.x & 31;
    if (gw >= NSAMP * NRELC * 256) return;
    int j = gw & 255;
    int ir = gw >> 8;
    int r = ir % NRELC, i = ir / NRELC;
    const float* wrow = &g_w1s[((size_t)i * 256 + j) * PREDIN + 522];
    const float* rrow = &rel[(size_t)r * 256];
    float s = 0.0f;
    for (int c = lane; c < 256; c += 32) s += rrow[c] * wrow[c];
    for (int o = 16; o; o >>= 1) s += __shfl_down_sync(0xffffffffu, s, o);
    if (lane == 0) g_Rc[gw] = s + g_cvec[i * 256 + j];
}

// C[100000 x 2560] = ext[100000 x 272] * Wcat[2560 x 272]^T   (fp32 SIMT tiled)
#define BM 128
#define BN 128
#define BK 16
__global__ void __launch_bounds__(256) k_gemm() {
    __shared__ float As[BK][BM + 4];
    __shared__ float Ws[BK][BN + 4];
    int bm = blockIdx.y * BM, bn = blockIdx.x * BN;
    int tid = threadIdx.x;
    int tm = (tid >> 4) << 3;
    int tn = (tid & 15) << 3;
    float acc[8][8];
#pragma unroll
    for (int x = 0; x < 8; x++)
#pragma unroll
        for (int y = 0; y < 8; y++) acc[x][y] = 0.0f;

    for (int k0 = 0; k0 < KP; k0 += BK) {
#pragma unroll
        for (int q = 0; q < 2; q++) {
            int lin = tid + q * 256;      // 0..511
            int row = lin >> 2;           // 0..127
            int kk = (lin & 3) << 2;      // 0,4,8,12
            int gr = bm + row;
            float4 va = make_float4(0.f, 0.f, 0.f, 0.f);
            if (gr < NN) va = *(const float4*)(&g_ext[(size_t)gr * KP + k0 + kk]);
            As[kk][row] = va.x; As[kk + 1][row] = va.y; As[kk + 2][row] = va.z; As[kk + 3][row] = va.w;
            float4 vb = *(const float4*)(&g_Wcat[(size_t)(bn + row) * KP + k0 + kk]);
            Ws[kk][row] = vb.x; Ws[kk + 1][row] = vb.y; Ws[kk + 2][row] = vb.z; Ws[kk + 3][row] = vb.w;
        }
        __syncthreads();
#pragma unroll
        for (int k = 0; k < BK; k++) {
            float ra[8], rb[8];
#pragma unroll
            for (int x = 0; x < 8; x++) { ra[x] = As[k][tm + x]; rb[x] = Ws[k][tn + x]; }
#pragma unroll
            for (int x = 0; x < 8; x++)
#pragma unroll
                for (int y = 0; y < 8; y++) acc[x][y] = fmaf(ra[x], rb[y], acc[x][y]);
        }
        __syncthreads();
    }
#pragma unroll
    for (int x = 0; x < 8; x++) {
        int gr = bm + tm + x;
        if (gr < NN) {
            float4* p = (float4*)&g_AB[(size_t)gr * CAB + bn + tn];
            p[0] = make_float4(acc[x][0], acc[x][1], acc[x][2], acc[x][3]);
            p[1] = make_float4(acc[x][4], acc[x][5], acc[x][6], acc[x][7]);
        }
    }
}

__global__ void k_b2sum() {
    if (threadIdx.x == 0) {
        float s = 0.0f;
#pragma unroll
        for (int i = 0; i < NSAMP; i++) s += g_b2s[i];
        g_b2sum_buf[0] = s;
    }
}

// warp per edge, float4 loads: lane covers [lane*4, lane*4+4) in each 128-chunk
__global__ void __launch_bounds__(256) k_edge2(const int* __restrict__ h_id,
                                               const int* __restrict__ t_id,
                                               const int* __restrict__ r_id,
                                               float* __restrict__ out) {
    int gw = (blockIdx.x * blockDim.x + threadIdx.x) >> 5;
    int lane = threadIdx.x & 31;
    if (gw >= EE) return;
    int h = h_id[gw], t = t_id[gw], r = r_id[gw];
    const float4* ah = (const float4*)&g_AB[(size_t)h * CAB];
    const float4* bt = (const float4*)&g_AB[(size_t)t * CAB + 256];
    const float4* rc = (const float4*)&g_Rc[(size_t)r * 256];
    const float4* w2 = (const float4*)g_w2s;
    float acc = 0.0f;
#pragma unroll
    for (int i = 0; i < NSAMP; i++) {
        // per sample: 256 floats = 64 float4; lane handles q4 = lane, lane+32
        const float4* ahi = ah + i * 128;   // 512 floats = 128 float4 stride
        const float4* bti = bt + i * 128;
        const float4* rci = rc + (size_t)i * (NRELC * 64);
        const float4* w2i = w2 + i * 64;
#pragma unroll
        for (int u = 0; u < 2; u++) {
            int q4 = lane + 32 * u;
            float4 a = ahi[q4];
            float4 b = bti[q4];
            float4 c = rci[q4];
            float4 w = w2i[q4];
            float v0 = fmaxf(a.x + b.x + c.x, 0.0f);
            float v1 = fmaxf(a.y + b.y + c.y, 0.0f);
            float v2 = fmaxf(a.z + b.z + c.z, 0.0f);
            float v3 = fmaxf(a.w + b.w + c.w, 0.0f);
            acc = fmaf(v0, w.x, acc);
            acc = fmaf(v1, w.y, acc);
            acc = fmaf(v2, w.z, acc);
            acc = fmaf(v3, w.w, acc);
        }
    }
    for (int o = 16; o; o >>= 1) acc += __shfl_down_sync(0xffffffffu, acc, o);
    if (lane == 0) out[gw] = (acc + g_b2sum_buf[0]) * 0.2f;
}

// ---------------- host ----------------
extern "C" void kernel_launch(void* const* d_in, const int* in_sizes, int n_in,
                              void* d_out, int out_size) {
    // input layout: if the scalar num_non_text_entities survived serialization
    // there are 17 inputs; if it was dropped, 16 (everything after index 4 shifts).
    int sh = (n_in >= 17) ? 0 : -1;
    const int*   h_id   = (const int*)d_in[0];
    const int*   r_id   = (const int*)d_in[1];
    const int*   t_id   = (const int*)d_in[2];
    const float* q_emb  = (const float*)d_in[3];
    const float* ent    = (const float*)d_in[4];
    const float* rel    = (const float*)d_in[6 + sh];
    const float* topic  = (const float*)d_in[7 + sh];
    const float* nontxt = (const float*)d_in[8 + sh];
    const float* w1mu   = (const float*)d_in[9 + sh];
    const float* w1rho  = (const float*)d_in[10 + sh];
    const float* b1mu   = (const float*)d_in[11 + sh];
    const float* b1rho  = (const float*)d_in[12 + sh];
    const float* w2mu   = (const float*)d_in[13 + sh];
    const float* w2rho  = (const float*)d_in[14 + sh];
    const float* b2mu   = (const float*)d_in[15 + sh];
    const float* b2rho  = (const float*)d_in[16 + sh];
    float* out = (float*)d_out;

    // derive JAX keys on host (threefry_partitionable=True semantics):
    // key(42) = (0,42); fold_in(key, i) = enc(key, (0, i));
    // split(folded, 4)[j] = both words of enc(folded, (0, j))
    Keys K;
    for (int i = 0; i < NSAMP; i++) {
        unsigned f0, f1;
        tf2x32(0u, 42u, 0u, (unsigned)i, f0, f1);
        for (int jj = 0; jj < 4; jj++) {
            unsigned a, b;
            tf2x32(f0, f1, 0u, (unsigned)jj, a, b);
            K.k[i][jj][0] = a; K.k[i][jj][1] = b;
        }
    }

    const int T = 256;
    // graph features
    k_zero<<<(NN * 2 + T - 1) / T, T>>>();
    k_scat1<<<(EE + T - 1) / T, T>>>(h_id, t_id, topic);
    {
        long long tot = (long long)NN * KP;
        k_build1<<<(unsigned)((tot + T - 1) / T), T>>>(ent, nontxt, topic);
    }
    k_scat2<<<(EE + T - 1) / T, T>>>(h_id, t_id);
    k_fill2<<<(NN * 2 + T - 1) / T, T>>>();

    // weight sampling (partitionable threefry)
    {
        dim3 g((W1FLAT + 513 + T - 1) / T, NSAMP);
        k_sample<<<g, T>>>(K, w1mu, w1rho, b1mu, b1rho, w2mu, w2rho, b2mu, b2rho);
    }
    {
        long long tot = (long long)CAB * KP;
        k_build_wcat<<<(unsigned)((tot + T - 1) / T), T>>>();
    }
    k_cvec<<<(NSAMP * 256 * 32 + T - 1) / T, T>>>(q_emb);
    k_rc<<<(NSAMP * NRELC * 256 * 32 + T - 1) / T, T>>>(rel);
    k_b2sum<<<1, 32>>>();

    // big GEMM: [100000 x 272] x [2560 x 272]^T
    {
        dim3 g(CAB / BN, (NN + BM - 1) / BM);
        k_gemm<<<g, 256>>>();
    }

    // edge stage: warp per edge
    {
        long long threads = (long long)EE * 32;
        k_edge2<<<(unsigned)((threads + T - 1) / T), T>>>(h_id, t_id, r_id, out);
    }
}

// round 7
// speedup vs baseline: 1.6707x; 1.6707x over previous
#include <cuda_runtime.h>
#include <cstdint>

// ---------------- problem constants ----------------
#define EE      500000
#define NN      100000
#define NTEXT   90000
#define EMBD    256
#define NRELC   500
#define KE      266      // h_e feature width
#define KP      272      // padded to /16
#define NSAMP   5
#define PREDIN  1044
#define W1FLAT  267264   // 256*1044
#define CAB     2560     // 5 samples * (256 A + 256 B)

// ---------------- device scratch (static, allowed) ----------------
__device__ float g_ext[(size_t)NN * KP];        // node features, padded
__device__ float g_AB[(size_t)NN * CAB];        // per-node per-sample A|B  (1.02 GB)
__device__ float g_w1s[(size_t)NSAMP * W1FLAT]; // sampled w1 (flat per sample)
__device__ float g_b1s[NSAMP * 256];
__device__ float g_w2s[NSAMP * 256];
__device__ float g_b2s[NSAMP];
__device__ float g_cvec[NSAMP * 256];           // q@Wq^T + b1
__device__ float g_Rc[(size_t)NSAMP * NRELC * 256];
__device__ float g_Wcat[(size_t)CAB * KP];      // GEMM B matrix (row-major, K-contig)
__device__ float g_sumA[NN * 2];
__device__ float g_sumB[NN * 2];
__device__ float g_degT[NN];
__device__ float g_degH[NN];
__device__ float g_b2sum_buf[1];

struct Keys { unsigned int k[NSAMP][4][2]; };

// ---------------- threefry2x32 (JAX-exact) ----------------
__host__ __device__ __forceinline__ unsigned int rotl32(unsigned int x, int r) {
    return (x << r) | (x >> (32 - r));
}
__host__ __device__ __forceinline__ void tf2x32(unsigned int k0, unsigned int k1,
                                                unsigned int x0, unsigned int x1,
                                                unsigned int& o0, unsigned int& o1) {
    unsigned int ks2 = k0 ^ k1 ^ 0x1BD11BDAu;
    x0 += k0; x1 += k1;
#define TFR(r) { x0 += x1; x1 = rotl32(x1, r); x1 ^= x0; }
    TFR(13) TFR(15) TFR(26) TFR(6)   x0 += k1;  x1 += ks2 + 1u;
    TFR(17) TFR(29) TFR(16) TFR(24)  x0 += ks2; x1 += k0 + 2u;
    TFR(13) TFR(15) TFR(26) TFR(6)   x0 += k0;  x1 += k1 + 3u;
    TFR(17) TFR(29) TFR(16) TFR(24)  x0 += k1;  x1 += ks2 + 4u;
    TFR(13) TFR(15) TFR(26) TFR(6)   x0 += ks2; x1 += k0 + 5u;
#undef TFR
    o0 = x0; o1 = x1;
}

// XLA f32 ErfInv (Giles polynomial) — matches jax.lax.erf_inv on f32
__device__ __forceinline__ float erfinv_f32(float x) {
    float w = -log1pf(-x * x);
    float p;
    if (w < 5.0f) {
        w -= 2.5f;
        p = 2.81022636e-08f;
        p = fmaf(p, w, 3.43273939e-07f);
        p = fmaf(p, w, -3.5233877e-06f);
        p = fmaf(p, w, -4.39150654e-06f);
        p = fmaf(p, w, 0.00021858087f);
        p = fmaf(p, w, -0.00125372503f);
        p = fmaf(p, w, -0.00417768164f);
        p = fmaf(p, w, 0.246640727f);
        p = fmaf(p, w, 1.50140941f);
    } else {
        w = sqrtf(w) - 3.0f;
        p = -0.000200214257f;
        p = fmaf(p, w, 0.000100950558f);
        p = fmaf(p, w, 0.00134934322f);
        p = fmaf(p, w, -0.00367342844f);
        p = fmaf(p, w, 0.00573950773f);
        p = fmaf(p, w, -0.0076224613f);
        p = fmaf(p, w, 0.00943887047f);
        p = fmaf(p, w, 1.00167406f);
        p = fmaf(p, w, 2.83297682f);
    }
    return p * x;
}

// jax.random.normal bit path
__device__ __forceinline__ float bits_to_normal(unsigned int b) {
    float f01 = __uint_as_float((b >> 9) | 0x3f800000u) - 1.0f;
    float u = __fadd_rn(__fmul_rn(f01, 2.0f), -0.99999994f);
    u = fmaxf(-0.99999994f, u);
    return __fmul_rn(1.41421356237f, erfinv_f32(u));
}

__device__ __forceinline__ float softplusf(float x) {
    return fmaxf(x, 0.0f) + log1pf(expf(-fabsf(x)));
}

// fp32 -> tf32 (round-to-nearest), result stored as float bit pattern
__device__ __forceinline__ float f2tf32(float x) {
    uint32_t r;
    asm("cvt.rna.tf32.f32 %0, %1;" : "=r"(r) : "f"(x));
    return __uint_as_float(r);
}

__device__ __forceinline__ void mma_tf32(float* c, const uint32_t* a, const uint32_t* b) {
    asm volatile(
        "mma.sync.aligned.m16n8k8.row.col.f32.tf32.tf32.f32 "
        "{%0,%1,%2,%3}, {%4,%5,%6,%7}, {%8,%9}, {%0,%1,%2,%3};\n"
        : "+f"(c[0]), "+f"(c[1]), "+f"(c[2]), "+f"(c[3])
        : "r"(a[0]), "r"(a[1]), "r"(a[2]), "r"(a[3]), "r"(b[0]), "r"(b[1]));
}

// ---------------- kernels ----------------
__global__ void k_zero() {
    int i = blockIdx.x * blockDim.x + threadIdx.x;
    if (i < NN * 2) { g_sumA[i] = 0.0f; g_sumB[i] = 0.0f; }
    if (i < NN)     { g_degT[i] = 0.0f; g_degH[i] = 0.0f; }
}

__global__ void k_scat1(const int* __restrict__ h_id, const int* __restrict__ t_id,
                        const float* __restrict__ topic) {
    int e = blockIdx.x * blockDim.x + threadIdx.x;
    if (e >= EE) return;
    int h = h_id[e], t = t_id[e];
    float x0 = topic[h * 2], x1 = topic[h * 2 + 1];
    atomicAdd(&g_sumA[t * 2], x0); atomicAdd(&g_sumA[t * 2 + 1], x1);
    float y0 = topic[t * 2], y1 = topic[t * 2 + 1];
    atomicAdd(&g_sumB[h * 2], y0); atomicAdd(&g_sumB[h * 2 + 1], y1);
    atomicAdd(&g_degT[t], 1.0f);
    atomicAdd(&g_degH[h], 1.0f);
}

__global__ void k_build1(const float* __restrict__ ent, const float* __restrict__ nontext,
                         const float* __restrict__ topic) {
    long long idx = (long long)blockIdx.x * blockDim.x + threadIdx.x;
    if (idx >= (long long)NN * KP) return;
    int n = (int)(idx / KP), c = (int)(idx % KP);
    float v = 0.0f;
    if (c < 256) {
        v = (n < NTEXT) ? ent[(size_t)n * 256 + c] : nontext[c];
    } else if (c < 258) {
        v = topic[n * 2 + (c - 256)];
    } else if (c < 260) {
        int k = c - 258;
        v = g_sumA[n * 2 + k] / fmaxf(g_degT[n], 1.0f);
        g_sumA[n * 2 + k] = 0.0f;
    } else if (c >= 262 && c < 264) {
        int k = c - 262;
        v = g_sumB[n * 2 + k] / fmaxf(g_degH[n], 1.0f);
        g_sumB[n * 2 + k] = 0.0f;
    }
    g_ext[(size_t)n * KP + c] = v;
}

__global__ void k_scat2(const int* __restrict__ h_id, const int* __restrict__ t_id) {
    int e = blockIdx.x * blockDim.x + threadIdx.x;
    if (e >= EE) return;
    int h = h_id[e], t = t_id[e];
    float a0 = g_ext[(size_t)h * KP + 258], a1 = g_ext[(size_t)h * KP + 259];
    atomicAdd(&g_sumA[t * 2], a0); atomicAdd(&g_sumA[t * 2 + 1], a1);
    float b0 = g_ext[(size_t)t * KP + 262], b1v = g_ext[(size_t)t * KP + 263];
    atomicAdd(&g_sumB[h * 2], b0); atomicAdd(&g_sumB[h * 2 + 1], b1v);
}

__global__ void k_fill2() {
    int idx = blockIdx.x * blockDim.x + threadIdx.x;
    if (idx >= NN * 2) return;
    int n = idx >> 1, k = idx & 1;
    g_ext[(size_t)n * KP + 260 + k] = g_sumA[n * 2 + k] / fmaxf(g_degT[n], 1.0f);
    g_ext[(size_t)n * KP + 264 + k] = g_sumB[n * 2 + k] / fmaxf(g_degH[n], 1.0f);
}

// PARTITIONABLE threefry (JAX >= 0.4.30 default)
__global__ void k_sample(Keys K,
                         const float* __restrict__ w1mu, const float* __restrict__ w1rho,
                         const float* __restrict__ b1mu, const float* __restrict__ b1rho,
                         const float* __restrict__ w2mu, const float* __restrict__ w2rho,
                         const float* __restrict__ b2mu, const float* __restrict__ b2rho) {
    int i = blockIdx.y;
    int j = blockIdx.x * blockDim.x + threadIdx.x;
    unsigned int v0, v1;
    if (j < W1FLAT) {
        tf2x32(K.k[i][0][0], K.k[i][0][1], 0u, (unsigned)j, v0, v1);
        float z = bits_to_normal(v0 ^ v1);
        g_w1s[(size_t)i * W1FLAT + j] = w1mu[j] + z * softplusf(w1rho[j]);
    } else if (j < W1FLAT + 256) {
        int jj = j - W1FLAT;
        tf2x32(K.k[i][1][0], K.k[i][1][1], 0u, (unsigned)jj, v0, v1);
        g_b1s[i * 256 + jj] = b1mu[jj] + bits_to_normal(v0 ^ v1) * softplusf(b1rho[jj]);
    } else if (j < W1FLAT + 512) {
        int jj = j - W1FLAT - 256;
        tf2x32(K.k[i][2][0], K.k[i][2][1], 0u, (unsigned)jj, v0, v1);
        g_w2s[i * 256 + jj] = w2mu[jj] + bits_to_normal(v0 ^ v1) * softplusf(w2rho[jj]);
    } else if (j == W1FLAT + 512) {
        tf2x32(K.k[i][3][0], K.k[i][3][1], 0u, 0u, v0, v1);
        g_b2s[i] = b2mu[0] + bits_to_normal(v0 ^ v1) * softplusf(b2rho[0]);
    }
}

__global__ void k_build_wcat() {
    long long idx = (long long)blockIdx.x * blockDim.x + threadIdx.x;
    if (idx >= (long long)CAB * KP) return;
    int n = (int)(idx / KP), c = (int)(idx % KP);
    float v = 0.0f;
    if (c < KE) {
        int i = n >> 9, jj = n & 511;
        int row = (jj < 256) ? jj : (jj - 256);
        int off = (jj < 256) ? 256 : 778;
        v = g_w1s[((size_t)i * 256 + row) * PREDIN + off + c];
    }
    g_Wcat[idx] = v;
}

__global__ void k_cvec(const float* __restrict__ q) {
    int gw = (blockIdx.x * blockDim.x + threadIdx.x) >> 5;
    int lane = threadIdx.x & 31;
    if (gw >= NSAMP * 256) return;
    int i = gw >> 8, j = gw & 255;
    const float* wrow = &g_w1s[((size_t)i * 256 + j) * PREDIN];
    float s = 0.0f;
    for (int c = lane; c < 256; c += 32) s += q[c] * wrow[c];
    for (int o = 16; o; o >>= 1) s += __shfl_down_sync(0xffffffffu, s, o);
    if (lane == 0) g_cvec[i * 256 + j] = s + g_b1s[i * 256 + j];
}

__global__ void k_rc(const float* __restrict__ rel) {
    int gw = (blockIdx.x * blockDim.x + threadIdx.x) >> 5;
    int lane = threadIdx.x & 31;
    if (gw >= NSAMP * NRELC * 256) return;
    int j = gw & 255;
    int ir = gw >> 8;
    int r = ir % NRELC, i = ir / NRELC;
    const float* wrow = &g_w1s[((size_t)i * 256 + j) * PREDIN + 522];
    const float* rrow = &rel[(size_t)r * 256];
    float s = 0.0f;
    for (int c = lane; c < 256; c += 32) s += rrow[c] * wrow[c];
    for (int o = 16; o; o >>= 1) s += __shfl_down_sync(0xffffffffu, s, o);
    if (lane == 0) g_Rc[gw] = s + g_cvec[i * 256 + j];
}

// ---------------- TF32 tensor-core GEMM ----------------
// C[100000 x 2560] = ext[100000 x 272] * Wcat[2560 x 272]^T
// block tile 128x128, BK=16; 8 warps as 2(m) x 4(n); warp tile 64x32 = 4x4 m16n8k8
#define BM 128
#define BN 128
#define BK 16
__global__ void __launch_bounds__(256) k_gemm_tf32() {
    __shared__ float As[BK][BM + 4];
    __shared__ float Bs[BK][BN + 4];
    int bm = blockIdx.y * BM, bn = blockIdx.x * BN;
    int tid = threadIdx.x;
    int wid = tid >> 5, lane = tid & 31;
    int warp_m = wid >> 2;    // 0..1
    int warp_n = wid & 3;     // 0..3
    int lr = lane >> 2;       // 0..7
    int lc = lane & 3;        // 0..3

    float acc[4][4][4];
#pragma unroll
    for (int mt = 0; mt < 4; mt++)
#pragma unroll
        for (int nt = 0; nt < 4; nt++)
#pragma unroll
            for (int c = 0; c < 4; c++) acc[mt][nt][c] = 0.0f;

    for (int k0 = 0; k0 < KP; k0 += BK) {
#pragma unroll
        for (int q = 0; q < 2; q++) {
            int lin = tid + q * 256;      // 0..511
            int row = lin >> 2;           // 0..127
            int kk = (lin & 3) << 2;      // 0,4,8,12
            int gr = bm + row;
            float4 va = make_float4(0.f, 0.f, 0.f, 0.f);
            if (gr < NN) va = *(const float4*)(&g_ext[(size_t)gr * KP + k0 + kk]);
            As[kk][row]     = f2tf32(va.x);
            As[kk + 1][row] = f2tf32(va.y);
            As[kk + 2][row] = f2tf32(va.z);
            As[kk + 3][row] = f2tf32(va.w);
            float4 vb = *(const float4*)(&g_Wcat[(size_t)(bn + row) * KP + k0 + kk]);
            Bs[kk][row]     = f2tf32(vb.x);
            Bs[kk + 1][row] = f2tf32(vb.y);
            Bs[kk + 2][row] = f2tf32(vb.z);
            Bs[kk + 3][row] = f2tf32(vb.w);
        }
        __syncthreads();
#pragma unroll
        for (int ks = 0; ks < 2; ks++) {
            int kb = ks * 8;
            uint32_t af[4][4];
#pragma unroll
            for (int mt = 0; mt < 4; mt++) {
                int m0 = warp_m * 64 + mt * 16;
                af[mt][0] = __float_as_uint(As[kb + lc][m0 + lr]);
                af[mt][1] = __float_as_uint(As[kb + lc][m0 + lr + 8]);
                af[mt][2] = __float_as_uint(As[kb + lc + 4][m0 + lr]);
                af[mt][3] = __float_as_uint(As[kb + lc + 4][m0 + lr + 8]);
            }
            uint32_t bf[4][2];
#pragma unroll
            for (int nt = 0; nt < 4; nt++) {
                int n0 = warp_n * 32 + nt * 8;
                bf[nt][0] = __float_as_uint(Bs[kb + lc][n0 + lr]);
                bf[nt][1] = __float_as_uint(Bs[kb + lc + 4][n0 + lr]);
            }
#pragma unroll
            for (int mt = 0; mt < 4; mt++)
#pragma unroll
                for (int nt = 0; nt < 4; nt++)
                    mma_tf32(acc[mt][nt], af[mt], bf[nt]);
        }
        __syncthreads();
    }

    // store: c0 at (m0+lr, n0+2*lc), c1 col+1, c2/c3 at row+8
#pragma unroll
    for (int mt = 0; mt < 4; mt++) {
#pragma unroll
        for (int nt = 0; nt < 4; nt++) {
            int col = bn + warp_n * 32 + nt * 8 + lc * 2;
            int gr0 = bm + warp_m * 64 + mt * 16 + lr;
            if (gr0 < NN) {
                float2 v = make_float2(acc[mt][nt][0], acc[mt][nt][1]);
                *(float2*)&g_AB[(size_t)gr0 * CAB + col] = v;
            }
            int gr1 = gr0 + 8;
            if (gr1 < NN) {
                float2 v = make_float2(acc[mt][nt][2], acc[mt][nt][3]);
                *(float2*)&g_AB[(size_t)gr1 * CAB + col] = v;
            }
        }
    }
}

__global__ void k_b2sum() {
    if (threadIdx.x == 0) {
        float s = 0.0f;
#pragma unroll
        for (int i = 0; i < NSAMP; i++) s += g_b2s[i];
        g_b2sum_buf[0] = s;
    }
}

// warp per edge, float4 loads
__global__ void __launch_bounds__(256) k_edge2(const int* __restrict__ h_id,
                                               const int* __restrict__ t_id,
                                               const int* __restrict__ r_id,
                                               float* __restrict__ out) {
    int gw = (blockIdx.x * blockDim.x + threadIdx.x) >> 5;
    int lane = threadIdx.x & 31;
    if (gw >= EE) return;
    int h = h_id[gw], t = t_id[gw], r = r_id[gw];
    const float4* ah = (const float4*)&g_AB[(size_t)h * CAB];
    const float4* bt = (const float4*)&g_AB[(size_t)t * CAB + 256];
    const float4* rc = (const float4*)&g_Rc[(size_t)r * 256];
    const float4* w2 = (const float4*)g_w2s;
    float acc = 0.0f;
#pragma unroll
    for (int i = 0; i < NSAMP; i++) {
        const float4* ahi = ah + i * 128;
        const float4* bti = bt + i * 128;
        const float4* rci = rc + (size_t)i * (NRELC * 64);
        const float4* w2i = w2 + i * 64;
#pragma unroll
        for (int u = 0; u < 2; u++) {
            int q4 = lane + 32 * u;
            float4 a = ahi[q4];
            float4 b = bti[q4];
            float4 c = rci[q4];
            float4 w = w2i[q4];
            float v0 = fmaxf(a.x + b.x + c.x, 0.0f);
            float v1 = fmaxf(a.y + b.y + c.y, 0.0f);
            float v2 = fmaxf(a.z + b.z + c.z, 0.0f);
            float v3 = fmaxf(a.w + b.w + c.w, 0.0f);
            acc = fmaf(v0, w.x, acc);
            acc = fmaf(v1, w.y, acc);
            acc = fmaf(v2, w.z, acc);
            acc = fmaf(v3, w.w, acc);
        }
    }
    for (int o = 16; o; o >>= 1) acc += __shfl_down_sync(0xffffffffu, acc, o);
    if (lane == 0) out[gw] = (acc + g_b2sum_buf[0]) * 0.2f;
}

// ---------------- host ----------------
extern "C" void kernel_launch(void* const* d_in, const int* in_sizes, int n_in,
                              void* d_out, int out_size) {
    int sh = (n_in >= 17) ? 0 : -1;
    const int*   h_id   = (const int*)d_in[0];
    const int*   r_id   = (const int*)d_in[1];
    const int*   t_id   = (const int*)d_in[2];
    const float* q_emb  = (const float*)d_in[3];
    const float* ent    = (const float*)d_in[4];
    const float* rel    = (const float*)d_in[6 + sh];
    const float* topic  = (const float*)d_in[7 + sh];
    const float* nontxt = (const float*)d_in[8 + sh];
    const float* w1mu   = (const float*)d_in[9 + sh];
    const float* w1rho  = (const float*)d_in[10 + sh];
    const float* b1mu   = (const float*)d_in[11 + sh];
    const float* b1rho  = (const float*)d_in[12 + sh];
    const float* w2mu   = (const float*)d_in[13 + sh];
    const float* w2rho  = (const float*)d_in[14 + sh];
    const float* b2mu   = (const float*)d_in[15 + sh];
    const float* b2rho  = (const float*)d_in[16 + sh];
    float* out = (float*)d_out;

    // JAX keys (threefry_partitionable=True): key(42)=(0,42);
    // fold_in(key,i)=enc(key,(0,i)); split(folded,4)[j]=both words of enc(folded,(0,j))
    Keys K;
    for (int i = 0; i < NSAMP; i++) {
        unsigned f0, f1;
        tf2x32(0u, 42u, 0u, (unsigned)i, f0, f1);
        for (int jj = 0; jj < 4; jj++) {
            unsigned a, b;
            tf2x32(f0, f1, 0u, (unsigned)jj, a, b);
            K.k[i][jj][0] = a; K.k[i][jj][1] = b;
        }
    }

    const int T = 256;
    // graph features
    k_zero<<<(NN * 2 + T - 1) / T, T>>>();
    k_scat1<<<(EE + T - 1) / T, T>>>(h_id, t_id, topic);
    {
        long long tot = (long long)NN * KP;
        k_build1<<<(unsigned)((tot + T - 1) / T), T>>>(ent, nontxt, topic);
    }
    k_scat2<<<(EE + T - 1) / T, T>>>(h_id, t_id);
    k_fill2<<<(NN * 2 + T - 1) / T, T>>>();

    // weight sampling (partitionable threefry)
    {
        dim3 g((W1FLAT + 513 + T - 1) / T, NSAMP);
        k_sample<<<g, T>>>(K, w1mu, w1rho, b1mu, b1rho, w2mu, w2rho, b2mu, b2rho);
    }
    {
        long long tot = (long long)CAB * KP;
        k_build_wcat<<<(unsigned)((tot + T - 1) / T), T>>>();
    }
    k_cvec<<<(NSAMP * 256 * 32 + T - 1) / T, T>>>(q_emb);
    k_rc<<<(NSAMP * NRELC * 256 * 32 + T - 1) / T, T>>>(rel);
    k_b2sum<<<1, 32>>>();

    // big GEMM: [100000 x 272] x [2560 x 272]^T  (TF32 tensor cores)
    {
        dim3 g(CAB / BN, (NN + BM - 1) / BM);
        k_gemm_tf32<<<g, 256>>>();
    }

    // edge stage: warp per edge
    {
        long long threads = (long long)EE * 32;
        k_edge2<<<(unsigned)((threads + T - 1) / T), T>>>(h_id, t_id, r_id, out);
    }
}

// round 8
// speedup vs baseline: 2.7006x; 1.6165x over previous
#include <cuda_runtime.h>
#include <cuda_fp16.h>
#include <cstdint>

// ---------------- problem constants ----------------
#define EE      500000
#define NN      100000
#define NTEXT   90000
#define EMBD    256
#define NRELC   500
#define KE      266      // h_e feature width
#define KP      272      // padded to /16
#define NSAMP   5
#define PREDIN  1044
#define W1FLAT  267264   // 256*1044
#define CAB     2560     // 5 samples * (256 A + 256 B)

// ---------------- device scratch (static, allowed) ----------------
__device__ __half g_ext[(size_t)NN * KP];       // node features (fp16), padded
__device__ __half g_AB[(size_t)NN * CAB];       // per-node per-sample A|B (fp16, 512MB)
__device__ __half g_Wcat[(size_t)CAB * KP];     // GEMM B matrix (fp16, K-contig)
__device__ float g_w1s[(size_t)NSAMP * W1FLAT]; // sampled w1 (flat per sample)
__device__ float g_b1s[NSAMP * 256];
__device__ float g_w2s[NSAMP * 256];
__device__ float g_b2s[NSAMP];
__device__ float g_cvec[NSAMP * 256];           // q@Wq^T + b1
__device__ float g_Rc[(size_t)NSAMP * NRELC * 256];
__device__ float g_sumA[NN * 2];
__device__ float g_sumB[NN * 2];
__device__ float g_degT[NN];
__device__ float g_degH[NN];
__device__ float g_b2sum_buf[1];

struct Keys { unsigned int k[NSAMP][4][2]; };

// ---------------- threefry2x32 (JAX-exact) ----------------
__host__ __device__ __forceinline__ unsigned int rotl32(unsigned int x, int r) {
    return (x << r) | (x >> (32 - r));
}
__host__ __device__ __forceinline__ void tf2x32(unsigned int k0, unsigned int k1,
                                                unsigned int x0, unsigned int x1,
                                                unsigned int& o0, unsigned int& o1) {
    unsigned int ks2 = k0 ^ k1 ^ 0x1BD11BDAu;
    x0 += k0; x1 += k1;
#define TFR(r) { x0 += x1; x1 = rotl32(x1, r); x1 ^= x0; }
    TFR(13) TFR(15) TFR(26) TFR(6)   x0 += k1;  x1 += ks2 + 1u;
    TFR(17) TFR(29) TFR(16) TFR(24)  x0 += ks2; x1 += k0 + 2u;
    TFR(13) TFR(15) TFR(26) TFR(6)   x0 += k0;  x1 += k1 + 3u;
    TFR(17) TFR(29) TFR(16) TFR(24)  x0 += k1;  x1 += ks2 + 4u;
    TFR(13) TFR(15) TFR(26) TFR(6)   x0 += ks2; x1 += k0 + 5u;
#undef TFR
    o0 = x0; o1 = x1;
}

// XLA f32 ErfInv (Giles polynomial)
__device__ __forceinline__ float erfinv_f32(float x) {
    float w = -log1pf(-x * x);
    float p;
    if (w < 5.0f) {
        w -= 2.5f;
        p = 2.81022636e-08f;
        p = fmaf(p, w, 3.43273939e-07f);
        p = fmaf(p, w, -3.5233877e-06f);
        p = fmaf(p, w, -4.39150654e-06f);
        p = fmaf(p, w, 0.00021858087f);
        p = fmaf(p, w, -0.00125372503f);
        p = fmaf(p, w, -0.00417768164f);
        p = fmaf(p, w, 0.246640727f);
        p = fmaf(p, w, 1.50140941f);
    } else {
        w = sqrtf(w) - 3.0f;
        p = -0.000200214257f;
        p = fmaf(p, w, 0.000100950558f);
        p = fmaf(p, w, 0.00134934322f);
        p = fmaf(p, w, -0.00367342844f);
        p = fmaf(p, w, 0.00573950773f);
        p = fmaf(p, w, -0.0076224613f);
        p = fmaf(p, w, 0.00943887047f);
        p = fmaf(p, w, 1.00167406f);
        p = fmaf(p, w, 2.83297682f);
    }
    return p * x;
}

__device__ __forceinline__ float bits_to_normal(unsigned int b) {
    float f01 = __uint_as_float((b >> 9) | 0x3f800000u) - 1.0f;
    float u = __fadd_rn(__fmul_rn(f01, 2.0f), -0.99999994f);
    u = fmaxf(-0.99999994f, u);
    return __fmul_rn(1.41421356237f, erfinv_f32(u));
}

__device__ __forceinline__ float softplusf(float x) {
    return fmaxf(x, 0.0f) + log1pf(expf(-fabsf(x)));
}

__device__ __forceinline__ void mma_f16(float* c, const uint32_t* a, const uint32_t* b) {
    asm volatile(
        "mma.sync.aligned.m16n8k16.row.col.f32.f16.f16.f32 "
        "{%0,%1,%2,%3}, {%4,%5,%6,%7}, {%8,%9}, {%0,%1,%2,%3};\n"
        : "+f"(c[0]), "+f"(c[1]), "+f"(c[2]), "+f"(c[3])
        : "r"(a[0]), "r"(a[1]), "r"(a[2]), "r"(a[3]), "r"(b[0]), "r"(b[1]));
}

// ---------------- kernels ----------------
__global__ void k_zero() {
    int i = blockIdx.x * blockDim.x + threadIdx.x;
    if (i < NN * 2) { g_sumA[i] = 0.0f; g_sumB[i] = 0.0f; }
    if (i < NN)     { g_degT[i] = 0.0f; g_degH[i] = 0.0f; }
}

__global__ void k_scat1(const int* __restrict__ h_id, const int* __restrict__ t_id,
                        const float* __restrict__ topic) {
    int e = blockIdx.x * blockDim.x + threadIdx.x;
    if (e >= EE) return;
    int h = h_id[e], t = t_id[e];
    float x0 = topic[h * 2], x1 = topic[h * 2 + 1];
    atomicAdd(&g_sumA[t * 2], x0); atomicAdd(&g_sumA[t * 2 + 1], x1);
    float y0 = topic[t * 2], y1 = topic[t * 2 + 1];
    atomicAdd(&g_sumB[h * 2], y0); atomicAdd(&g_sumB[h * 2 + 1], y1);
    atomicAdd(&g_degT[t], 1.0f);
    atomicAdd(&g_degH[h], 1.0f);
}

// fill ext (fp16); round-1 means in cols 258/259 (fwd), 262/263 (rev); reset sums
__global__ void k_build1(const float* __restrict__ ent, const float* __restrict__ nontext,
                         const float* __restrict__ topic) {
    long long idx = (long long)blockIdx.x * blockDim.x + threadIdx.x;
    if (idx >= (long long)NN * KP) return;
    int n = (int)(idx / KP), c = (int)(idx % KP);
    float v = 0.0f;
    if (c < 256) {
        v = (n < NTEXT) ? ent[(size_t)n * 256 + c] : nontext[c];
    } else if (c < 258) {
        v = topic[n * 2 + (c - 256)];
    } else if (c < 260) {
        int k = c - 258;
        v = g_sumA[n * 2 + k] / fmaxf(g_degT[n], 1.0f);
        g_sumA[n * 2 + k] = 0.0f;
    } else if (c >= 262 && c < 264) {
        int k = c - 262;
        v = g_sumB[n * 2 + k] / fmaxf(g_degH[n], 1.0f);
        g_sumB[n * 2 + k] = 0.0f;
    }
    g_ext[(size_t)n * KP + c] = __float2half_rn(v);
}

__global__ void k_scat2(const int* __restrict__ h_id, const int* __restrict__ t_id) {
    int e = blockIdx.x * blockDim.x + threadIdx.x;
    if (e >= EE) return;
    int h = h_id[e], t = t_id[e];
    float a0 = __half2float(g_ext[(size_t)h * KP + 258]);
    float a1 = __half2float(g_ext[(size_t)h * KP + 259]);
    atomicAdd(&g_sumA[t * 2], a0); atomicAdd(&g_sumA[t * 2 + 1], a1);
    float b0 = __half2float(g_ext[(size_t)t * KP + 262]);
    float b1v = __half2float(g_ext[(size_t)t * KP + 263]);
    atomicAdd(&g_sumB[h * 2], b0); atomicAdd(&g_sumB[h * 2 + 1], b1v);
}

__global__ void k_fill2() {
    int idx = blockIdx.x * blockDim.x + threadIdx.x;
    if (idx >= NN * 2) return;
    int n = idx >> 1, k = idx & 1;
    g_ext[(size_t)n * KP + 260 + k] = __float2half_rn(g_sumA[n * 2 + k] / fmaxf(g_degT[n], 1.0f));
    g_ext[(size_t)n * KP + 264 + k] = __float2half_rn(g_sumB[n * 2 + k] / fmaxf(g_degH[n], 1.0f));
}

// PARTITIONABLE threefry (JAX >= 0.4.30 default)
__global__ void k_sample(Keys K,
                         const float* __restrict__ w1mu, const float* __restrict__ w1rho,
                         const float* __restrict__ b1mu, const float* __restrict__ b1rho,
                         const float* __restrict__ w2mu, const float* __restrict__ w2rho,
                         const float* __restrict__ b2mu, const float* __restrict__ b2rho) {
    int i = blockIdx.y;
    int j = blockIdx.x * blockDim.x + threadIdx.x;
    unsigned int v0, v1;
    if (j < W1FLAT) {
        tf2x32(K.k[i][0][0], K.k[i][0][1], 0u, (unsigned)j, v0, v1);
        float z = bits_to_normal(v0 ^ v1);
        g_w1s[(size_t)i * W1FLAT + j] = w1mu[j] + z * softplusf(w1rho[j]);
    } else if (j < W1FLAT + 256) {
        int jj = j - W1FLAT;
        tf2x32(K.k[i][1][0], K.k[i][1][1], 0u, (unsigned)jj, v0, v1);
        g_b1s[i * 256 + jj] = b1mu[jj] + bits_to_normal(v0 ^ v1) * softplusf(b1rho[jj]);
    } else if (j < W1FLAT + 512) {
        int jj = j - W1FLAT - 256;
        tf2x32(K.k[i][2][0], K.k[i][2][1], 0u, (unsigned)jj, v0, v1);
        g_w2s[i * 256 + jj] = w2mu[jj] + bits_to_normal(v0 ^ v1) * softplusf(w2rho[jj]);
    } else if (j == W1FLAT + 512) {
        tf2x32(K.k[i][3][0], K.k[i][3][1], 0u, 0u, v0, v1);
        g_b2s[i] = b2mu[0] + bits_to_normal(v0 ^ v1) * softplusf(b2rho[0]);
    }
}

// Wcat[row=i*512+jj][c] (fp16): jj<256 -> w1 cols 256+c (h); jj>=256 -> cols 778+c (t)
__global__ void k_build_wcat() {
    long long idx = (long long)blockIdx.x * blockDim.x + threadIdx.x;
    if (idx >= (long long)CAB * KP) return;
    int n = (int)(idx / KP), c = (int)(idx % KP);
    float v = 0.0f;
    if (c < KE) {
        int i = n >> 9, jj = n & 511;
        int row = (jj < 256) ? jj : (jj - 256);
        int off = (jj < 256) ? 256 : 778;
        v = g_w1s[((size_t)i * 256 + row) * PREDIN + off + c];
    }
    g_Wcat[idx] = __float2half_rn(v);
}

__global__ void k_cvec(const float* __restrict__ q) {
    int gw = (blockIdx.x * blockDim.x + threadIdx.x) >> 5;
    int lane = threadIdx.x & 31;
    if (gw >= NSAMP * 256) return;
    int i = gw >> 8, j = gw & 255;
    const float* wrow = &g_w1s[((size_t)i * 256 + j) * PREDIN];
    float s = 0.0f;
    for (int c = lane; c < 256; c += 32) s += q[c] * wrow[c];
    for (int o = 16; o; o >>= 1) s += __shfl_down_sync(0xffffffffu, s, o);
    if (lane == 0) g_cvec[i * 256 + j] = s + g_b1s[i * 256 + j];
}

__global__ void k_rc(const float* __restrict__ rel) {
    int gw = (blockIdx.x * blockDim.x + threadIdx.x) >> 5;
    int lane = threadIdx.x & 31;
    if (gw >= NSAMP * NRELC * 256) return;
    int j = gw & 255;
    int ir = gw >> 8;
    int r = ir % NRELC, i = ir / NRELC;
    const float* wrow = &g_w1s[((size_t)i * 256 + j) * PREDIN + 522];
    const float* rrow = &rel[(size_t)r * 256];
    float s = 0.0f;
    for (int c = lane; c < 256; c += 32) s += rrow[c] * wrow[c];
    for (int o = 16; o; o >>= 1) s += __shfl_down_sync(0xffffffffu, s, o);
    if (lane == 0) g_Rc[gw] = s + g_cvec[i * 256 + j];
}

// ---------------- fp16 tensor-core GEMM ----------------
// C[100000 x 2560] = ext[100000 x 272] * Wcat[2560 x 272]^T
// block tile 128x128, BK=16 halves; 8 warps 2(m)x4(n); warp tile 64x32 = 4x4 m16n8k16
#define BM 128
#define BN 128
#define BK 16
#define BKP 24   // padded row stride in halves (48B, uint4-aligned)
__global__ void __launch_bounds__(256) k_gemm_f16() {
    __shared__ __half As[BM][BKP];
    __shared__ __half Bs[BN][BKP];
    int bm = blockIdx.y * BM, bn = blockIdx.x * BN;
    int tid = threadIdx.x;
    int wid = tid >> 5, lane = tid & 31;
    int warp_m = wid >> 2;    // 0..1
    int warp_n = wid & 3;     // 0..3
    int lr = lane >> 2;       // 0..7
    int lc = lane & 3;        // 0..3

    float acc[4][4][4];
#pragma unroll
    for (int mt = 0; mt < 4; mt++)
#pragma unroll
        for (int nt = 0; nt < 4; nt++)
#pragma unroll
            for (int c = 0; c < 4; c++) acc[mt][nt][c] = 0.0f;

    int lrow = tid >> 1;          // 0..127
    int lhof = (tid & 1) * 8;     // 0 or 8

    for (int k0 = 0; k0 < KP; k0 += BK) {
        {
            int gr = bm + lrow;
            uint4 va = make_uint4(0u, 0u, 0u, 0u);
            if (gr < NN) va = *(const uint4*)(&g_ext[(size_t)gr * KP + k0 + lhof]);
            *(uint4*)(&As[lrow][lhof]) = va;
            uint4 vb = *(const uint4*)(&g_Wcat[(size_t)(bn + lrow) * KP + k0 + lhof]);
            *(uint4*)(&Bs[lrow][lhof]) = vb;
        }
        __syncthreads();
        {
            uint32_t af[4][4];
#pragma unroll
            for (int mt = 0; mt < 4; mt++) {
                int m0 = warp_m * 64 + mt * 16;
                af[mt][0] = *(const uint32_t*)(&As[m0 + lr][lc * 2]);
                af[mt][1] = *(const uint32_t*)(&As[m0 + lr + 8][lc * 2]);
                af[mt][2] = *(const uint32_t*)(&As[m0 + lr][lc * 2 + 8]);
                af[mt][3] = *(const uint32_t*)(&As[m0 + lr + 8][lc * 2 + 8]);
            }
            uint32_t bf[4][2];
#pragma unroll
            for (int nt = 0; nt < 4; nt++) {
                int n0 = warp_n * 32 + nt * 8;
                bf[nt][0] = *(const uint32_t*)(&Bs[n0 + lr][lc * 2]);
                bf[nt][1] = *(const uint32_t*)(&Bs[n0 + lr][lc * 2 + 8]);
            }
#pragma unroll
            for (int mt = 0; mt < 4; mt++)
#pragma unroll
                for (int nt = 0; nt < 4; nt++)
                    mma_f16(acc[mt][nt], af[mt], bf[nt]);
        }
        __syncthreads();
    }

    // store fp16: c0,c1 at (m0+lr, col..col+1); c2,c3 at row+8
#pragma unroll
    for (int mt = 0; mt < 4; mt++) {
#pragma unroll
        for (int nt = 0; nt < 4; nt++) {
            int col = bn + warp_n * 32 + nt * 8 + lc * 2;
            int gr0 = bm + warp_m * 64 + mt * 16 + lr;
            if (gr0 < NN) {
                __half2 v = __floats2half2_rn(acc[mt][nt][0], acc[mt][nt][1]);
                *(__half2*)(&g_AB[(size_t)gr0 * CAB + col]) = v;
            }
            int gr1 = gr0 + 8;
            if (gr1 < NN) {
                __half2 v = __floats2half2_rn(acc[mt][nt][2], acc[mt][nt][3]);
                *(__half2*)(&g_AB[(size_t)gr1 * CAB + col]) = v;
            }
        }
    }
}

__global__ void k_b2sum() {
    if (threadIdx.x == 0) {
        float s = 0.0f;
#pragma unroll
        for (int i = 0; i < NSAMP; i++) s += g_b2s[i];
        g_b2sum_buf[0] = s;
    }
}

// warp per edge; fp16 AB: lane loads 8 halves (uint4) per A/B per sample
__global__ void __launch_bounds__(256) k_edge2(const int* __restrict__ h_id,
                                               const int* __restrict__ t_id,
                                               const int* __restrict__ r_id,
                                               float* __restrict__ out) {
    int gw = (blockIdx.x * blockDim.x + threadIdx.x) >> 5;
    int lane = threadIdx.x & 31;
    if (gw >= EE) return;
    int h = h_id[gw], t = t_id[gw], r = r_id[gw];
    const __half* ah = &g_AB[(size_t)h * CAB];
    const __half* bt = &g_AB[(size_t)t * CAB + 256];
    const float4* rc = (const float4*)&g_Rc[(size_t)r * 256];
    const float4* w2 = (const float4*)g_w2s;
    float acc = 0.0f;
#pragma unroll
    for (int i = 0; i < NSAMP; i++) {
        uint4 a4 = *(const uint4*)(ah + i * 512 + lane * 8);
        uint4 b4 = *(const uint4*)(bt + i * 512 + lane * 8);
        const float4* rci = rc + (size_t)i * (NRELC * 64);
        const float4* w2i = w2 + i * 64;
        float4 c0 = rci[lane * 2], c1 = rci[lane * 2 + 1];
        float4 w0 = w2i[lane * 2], w1 = w2i[lane * 2 + 1];
        const __half2* a2 = (const __half2*)&a4;
        const __half2* b2 = (const __half2*)&b4;
        float2 af0 = __half22float2(a2[0]), bf0 = __half22float2(b2[0]);
        float2 af1 = __half22float2(a2[1]), bf1 = __half22float2(b2[1]);
        float2 af2 = __half22float2(a2[2]), bf2 = __half22float2(b2[2]);
        float2 af3 = __half22float2(a2[3]), bf3 = __half22float2(b2[3]);
        acc = fmaf(fmaxf(af0.x + bf0.x + c0.x, 0.0f), w0.x, acc);
        acc = fmaf(fmaxf(af0.y + bf0.y + c0.y, 0.0f), w0.y, acc);
        acc = fmaf(fmaxf(af1.x + bf1.x + c0.z, 0.0f), w0.z, acc);
        acc = fmaf(fmaxf(af1.y + bf1.y + c0.w, 0.0f), w0.w, acc);
        acc = fmaf(fmaxf(af2.x + bf2.x + c1.x, 0.0f), w1.x, acc);
        acc = fmaf(fmaxf(af2.y + bf2.y + c1.y, 0.0f), w1.y, acc);
        acc = fmaf(fmaxf(af3.x + bf3.x + c1.z, 0.0f), w1.z, acc);
        acc = fmaf(fmaxf(af3.y + bf3.y + c1.w, 0.0f), w1.w, acc);
    }
    for (int o = 16; o; o >>= 1) acc += __shfl_down_sync(0xffffffffu, acc, o);
    if (lane == 0) out[gw] = (acc + g_b2sum_buf[0]) * 0.2f;
}

// ---------------- host ----------------
extern "C" void kernel_launch(void* const* d_in, const int* in_sizes, int n_in,
                              void* d_out, int out_size) {
    int sh = (n_in >= 17) ? 0 : -1;
    const int*   h_id   = (const int*)d_in[0];
    const int*   r_id   = (const int*)d_in[1];
    const int*   t_id   = (const int*)d_in[2];
    const float* q_emb  = (const float*)d_in[3];
    const float* ent    = (const float*)d_in[4];
    const float* rel    = (const float*)d_in[6 + sh];
    const float* topic  = (const float*)d_in[7 + sh];
    const float* nontxt = (const float*)d_in[8 + sh];
    const float* w1mu   = (const float*)d_in[9 + sh];
    const float* w1rho  = (const float*)d_in[10 + sh];
    const float* b1mu   = (const float*)d_in[11 + sh];
    const float* b1rho  = (const float*)d_in[12 + sh];
    const float* w2mu   = (const float*)d_in[13 + sh];
    const float* w2rho  = (const float*)d_in[14 + sh];
    const float* b2mu   = (const float*)d_in[15 + sh];
    const float* b2rho  = (const float*)d_in[16 + sh];
    float* out = (float*)d_out;

    // JAX keys (threefry_partitionable=True)
    Keys K;
    for (int i = 0; i < NSAMP; i++) {
        unsigned f0, f1;
        tf2x32(0u, 42u, 0u, (unsigned)i, f0, f1);
        for (int jj = 0; jj < 4; jj++) {
            unsigned a, b;
            tf2x32(f0, f1, 0u, (unsigned)jj, a, b);
            K.k[i][jj][0] = a; K.k[i][jj][1] = b;
        }
    }

    const int T = 256;
    // graph features
    k_zero<<<(NN * 2 + T - 1) / T, T>>>();
    k_scat1<<<(EE + T - 1) / T, T>>>(h_id, t_id, topic);
    {
        long long tot = (long long)NN * KP;
        k_build1<<<(unsigned)((tot + T - 1) / T), T>>>(ent, nontxt, topic);
    }
    k_scat2<<<(EE + T - 1) / T, T>>>(h_id, t_id);
    k_fill2<<<(NN * 2 + T - 1) / T, T>>>();

    // weight sampling (partitionable threefry)
    {
        dim3 g((W1FLAT + 513 + T - 1) / T, NSAMP);
        k_sample<<<g, T>>>(K, w1mu, w1rho, b1mu, b1rho, w2mu, w2rho, b2mu, b2rho);
    }
    {
        long long tot = (long long)CAB * KP;
        k_build_wcat<<<(unsigned)((tot + T - 1) / T), T>>>();
    }
    k_cvec<<<(NSAMP * 256 * 32 + T - 1) / T, T>>>(q_emb);
    k_rc<<<(NSAMP * NRELC * 256 * 32 + T - 1) / T, T>>>(rel);
    k_b2sum<<<1, 32>>>();

    // big GEMM: [100000 x 272] x [2560 x 272]^T  (fp16 tensor cores, fp32 accum)
    {
        dim3 g(CAB / BN, (NN + BM - 1) / BM);
        k_gemm_f16<<<g, 256>>>();
    }

    // edge stage: warp per edge
    {
        long long threads = (long long)EE * 32;
        k_edge2<<<(unsigned)((threads + T - 1) / T), T>>>(h_id, t_id, r_id, out);
    }
}

// round 11
// speedup vs baseline: 3.1180x; 1.1546x over previous
#include <cuda_runtime.h>
#include <cuda_fp16.h>
#include <cstdint>

// ---------------- problem constants ----------------
#define EE      500000
#define NN      100000
#define NP      100096   // NN padded to /128 (for guard-free GEMM tiles)
#define NTEXT   90000
#define NRELC   500
#define KE      266      // h_e feature width
#define KPAD    288      // K padded to /32 (9 x BK)
#define NSAMP   5
#define PREDIN  1044
#define W1FLAT  267264   // 256*1044
#define CAB     2560     // 5 samples * (256 A + 256 B)
#define NODEW   1280     // per-node halves in g_A / g_B (5 samples * 256)

// ---------------- device scratch (static, allowed) ----------------
__device__ __half g_ext[(size_t)NP * KPAD];     // node features (fp16), padded
__device__ __half g_A[(size_t)NP * NODEW];      // per-node A parts (fp16, contiguous samples)
__device__ __half g_B[(size_t)NP * NODEW];      // per-node B parts
__device__ __half g_Wcat[(size_t)CAB * KPAD];   // GEMM B matrix (fp16, K-contig)
__device__ float g_w1s[(size_t)NSAMP * W1FLAT]; // sampled w1 (flat per sample)
__device__ float g_b1s[NSAMP * 256];
__device__ float g_w2s[NSAMP * 256];
__device__ float g_b2s[NSAMP];
__device__ float g_cvec[NSAMP * 256];
__device__ float g_Rc[(size_t)NSAMP * NRELC * 256];
__device__ float g_sumA[NN * 2];
__device__ float g_sumB[NN * 2];
__device__ float g_degT[NN];
__device__ float g_degH[NN];
__device__ float g_b2sum_buf[1];

struct Keys { unsigned int k[NSAMP][4][2]; };

// ---------------- threefry2x32 (JAX-exact) ----------------
__host__ __device__ __forceinline__ unsigned int rotl32(unsigned int x, int r) {
    return (x << r) | (x >> (32 - r));
}
__host__ __device__ __forceinline__ void tf2x32(unsigned int k0, unsigned int k1,
                                                unsigned int x0, unsigned int x1,
                                                unsigned int& o0, unsigned int& o1) {
    unsigned int ks2 = k0 ^ k1 ^ 0x1BD11BDAu;
    x0 += k0; x1 += k1;
#define TFR(r) { x0 += x1; x1 = rotl32(x1, r); x1 ^= x0; }
    TFR(13) TFR(15) TFR(26) TFR(6)   x0 += k1;  x1 += ks2 + 1u;
    TFR(17) TFR(29) TFR(16) TFR(24)  x0 += ks2; x1 += k0 + 2u;
    TFR(13) TFR(15) TFR(26) TFR(6)   x0 += k0;  x1 += k1 + 3u;
    TFR(17) TFR(29) TFR(16) TFR(24)  x0 += k1;  x1 += ks2 + 4u;
    TFR(13) TFR(15) TFR(26) TFR(6)   x0 += ks2; x1 += k0 + 5u;
#undef TFR
    o0 = x0; o1 = x1;
}

// XLA f32 ErfInv (Giles polynomial)
__device__ __forceinline__ float erfinv_f32(float x) {
    float w = -log1pf(-x * x);
    float p;
    if (w < 5.0f) {
        w -= 2.5f;
        p = 2.81022636e-08f;
        p = fmaf(p, w, 3.43273939e-07f);
        p = fmaf(p, w, -3.5233877e-06f);
        p = fmaf(p, w, -4.39150654e-06f);
        p = fmaf(p, w, 0.00021858087f);
        p = fmaf(p, w, -0.00125372503f);
        p = fmaf(p, w, -0.00417768164f);
        p = fmaf(p, w, 0.246640727f);
        p = fmaf(p, w, 1.50140941f);
    } else {
        w = sqrtf(w) - 3.0f;
        p = -0.000200214257f;
        p = fmaf(p, w, 0.000100950558f);
        p = fmaf(p, w, 0.00134934322f);
        p = fmaf(p, w, -0.00367342844f);
        p = fmaf(p, w, 0.00573950773f);
        p = fmaf(p, w, -0.0076224613f);
        p = fmaf(p, w, 0.00943887047f);
        p = fmaf(p, w, 1.00167406f);
        p = fmaf(p, w, 2.83297682f);
    }
    return p * x;
}

__device__ __forceinline__ float bits_to_normal(unsigned int b) {
    float f01 = __uint_as_float((b >> 9) | 0x3f800000u) - 1.0f;
    float u = __fadd_rn(__fmul_rn(f01, 2.0f), -0.99999994f);
    u = fmaxf(-0.99999994f, u);
    return __fmul_rn(1.41421356237f, erfinv_f32(u));
}

__device__ __forceinline__ float softplusf(float x) {
    return fmaxf(x, 0.0f) + log1pf(expf(-fabsf(x)));
}

__device__ __forceinline__ void mma_f16(float* c, const uint32_t* a, const uint32_t* b) {
    asm volatile(
        "mma.sync.aligned.m16n8k16.row.col.f32.f16.f16.f32 "
        "{%0,%1,%2,%3}, {%4,%5,%6,%7}, {%8,%9}, {%0,%1,%2,%3};\n"
        : "+f"(c[0]), "+f"(c[1]), "+f"(c[2]), "+f"(c[3])
        : "r"(a[0]), "r"(a[1]), "r"(a[2]), "r"(a[3]), "r"(b[0]), "r"(b[1]));
}

__device__ __forceinline__ void ldsm_x4(uint32_t* r, const void* sptr) {
    uint32_t a = (uint32_t)__cvta_generic_to_shared(sptr);
    asm volatile("ldmatrix.sync.aligned.m8n8.x4.shared.b16 {%0,%1,%2,%3}, [%4];"
                 : "=r"(r[0]), "=r"(r[1]), "=r"(r[2]), "=r"(r[3]) : "r"(a));
}

__device__ __forceinline__ void cp16(const void* sdst, const void* gsrc) {
    uint32_t d = (uint32_t)__cvta_generic_to_shared(sdst);
    asm volatile("cp.async.cg.shared.global [%0], [%1], 16;\n" :: "r"(d), "l"(gsrc));
}
#define CP_COMMIT() asm volatile("cp.async.commit_group;\n")
#define CP_WAIT(n)  asm volatile("cp.async.wait_group %0;\n" :: "n"(n))

// ---------------- graph-feature kernels ----------------
__global__ void k_zero() {
    int i = blockIdx.x * blockDim.x + threadIdx.x;
    if (i < NN * 2) { g_sumA[i] = 0.0f; g_sumB[i] = 0.0f; }
    if (i < NN)     { g_degT[i] = 0.0f; g_degH[i] = 0.0f; }
}

__global__ void k_scat1(const int* __restrict__ h_id, const int* __restrict__ t_id,
                        const float* __restrict__ topic) {
    int e = blockIdx.x * blockDim.x + threadIdx.x;
    if (e >= EE) return;
    int h = h_id[e], t = t_id[e];
    float x0 = topic[h * 2], x1 = topic[h * 2 + 1];
    atomicAdd(&g_sumA[t * 2], x0); atomicAdd(&g_sumA[t * 2 + 1], x1);
    float y0 = topic[t * 2], y1 = topic[t * 2 + 1];
    atomicAdd(&g_sumB[h * 2], y0); atomicAdd(&g_sumB[h * 2 + 1], y1);
    atomicAdd(&g_degT[t], 1.0f);
    atomicAdd(&g_degH[h], 1.0f);
}

// fill ext (fp16, padded rows/cols zero); round-1 means in 258/259 (fwd), 262/263 (rev)
__global__ void k_build1(const float* __restrict__ ent, const float* __restrict__ nontext,
                         const float* __restrict__ topic) {
    long long idx = (long long)blockIdx.x * blockDim.x + threadIdx.x;
    if (idx >= (long long)NP * KPAD) return;
    int n = (int)(idx / KPAD), c = (int)(idx % KPAD);
    float v = 0.0f;
    if (n < NN) {
        if (c < 256) {
            v = (n < NTEXT) ? ent[(size_t)n * 256 + c] : nontext[c];
        } else if (c < 258) {
            v = topic[n * 2 + (c - 256)];
        } else if (c < 260) {
            int k = c - 258;
            v = g_sumA[n * 2 + k] / fmaxf(g_degT[n], 1.0f);
            g_sumA[n * 2 + k] = 0.0f;
        } else if (c >= 262 && c < 264) {
            int k = c - 262;
            v = g_sumB[n * 2 + k] / fmaxf(g_degH[n], 1.0f);
            g_sumB[n * 2 + k] = 0.0f;
        }
    }
    g_ext[(size_t)n * KPAD + c] = __float2half_rn(v);
}

__global__ void k_scat2(const int* __restrict__ h_id, const int* __restrict__ t_id) {
    int e = blockIdx.x * blockDim.x + threadIdx.x;
    if (e >= EE) return;
    int h = h_id[e], t = t_id[e];
    float a0 = __half2float(g_ext[(size_t)h * KPAD + 258]);
    float a1 = __half2float(g_ext[(size_t)h * KPAD + 259]);
    atomicAdd(&g_sumA[t * 2], a0); atomicAdd(&g_sumA[t * 2 + 1], a1);
    float b0 = __half2float(g_ext[(size_t)t * KPAD + 262]);
    float b1v = __half2float(g_ext[(size_t)t * KPAD + 263]);
    atomicAdd(&g_sumB[h * 2], b0); atomicAdd(&g_sumB[h * 2 + 1], b1v);
}

__global__ void k_fill2() {
    int idx = blockIdx.x * blockDim.x + threadIdx.x;
    if (idx >= NN * 2) return;
    int n = idx >> 1, k = idx & 1;
    g_ext[(size_t)n * KPAD + 260 + k] = __float2half_rn(g_sumA[n * 2 + k] / fmaxf(g_degT[n], 1.0f));
    g_ext[(size_t)n * KPAD + 264 + k] = __float2half_rn(g_sumB[n * 2 + k] / fmaxf(g_degH[n], 1.0f));
}

// PARTITIONABLE threefry (JAX >= 0.4.30 default)
__global__ void k_sample(Keys K,
                         const float* __restrict__ w1mu, const float* __restrict__ w1rho,
                         const float* __restrict__ b1mu, const float* __restrict__ b1rho,
                         const float* __restrict__ w2mu, const float* __restrict__ w2rho,
                         const float* __restrict__ b2mu, const float* __restrict__ b2rho) {
    int i = blockIdx.y;
    int j = blockIdx.x * blockDim.x + threadIdx.x;
    unsigned int v0, v1;
    if (j < W1FLAT) {
        tf2x32(K.k[i][0][0], K.k[i][0][1], 0u, (unsigned)j, v0, v1);
        float z = bits_to_normal(v0 ^ v1);
        g_w1s[(size_t)i * W1FLAT + j] = w1mu[j] + z * softplusf(w1rho[j]);
    } else if (j < W1FLAT + 256) {
        int jj = j - W1FLAT;
        tf2x32(K.k[i][1][0], K.k[i][1][1], 0u, (unsigned)jj, v0, v1);
        g_b1s[i * 256 + jj] = b1mu[jj] + bits_to_normal(v0 ^ v1) * softplusf(b1rho[jj]);
    } else if (j < W1FLAT + 512) {
        int jj = j - W1FLAT - 256;
        tf2x32(K.k[i][2][0], K.k[i][2][1], 0u, (unsigned)jj, v0, v1);
        g_w2s[i * 256 + jj] = w2mu[jj] + bits_to_normal(v0 ^ v1) * softplusf(w2rho[jj]);
    } else if (j == W1FLAT + 512) {
        tf2x32(K.k[i][3][0], K.k[i][3][1], 0u, 0u, v0, v1);
        g_b2s[i] = b2mu[0] + bits_to_normal(v0 ^ v1) * softplusf(b2rho[0]);
    }
}

// Wcat[row=i*512+jj][c] (fp16): jj<256 -> w1 cols 256+c (h); jj>=256 -> cols 778+c (t)
__global__ void k_build_wcat() {
    long long idx = (long long)blockIdx.x * blockDim.x + threadIdx.x;
    if (idx >= (long long)CAB * KPAD) return;
    int n = (int)(idx / KPAD), c = (int)(idx % KPAD);
    float v = 0.0f;
    if (c < KE) {
        int i = n >> 9, jj = n & 511;
        int row = (jj < 256) ? jj : (jj - 256);
        int off = (jj < 256) ? 256 : 778;
        v = g_w1s[((size_t)i * 256 + row) * PREDIN + off + c];
    }
    g_Wcat[idx] = __float2half_rn(v);
}

__global__ void k_cvec(const float* __restrict__ q) {
    int gw = (blockIdx.x * blockDim.x + threadIdx.x) >> 5;
    int lane = threadIdx.x & 31;
    if (gw >= NSAMP * 256) return;
    int i = gw >> 8, j = gw & 255;
    const float* wrow = &g_w1s[((size_t)i * 256 + j) * PREDIN];
    float s = 0.0f;
    for (int c = lane; c < 256; c += 32) s += q[c] * wrow[c];
    for (int o = 16; o; o >>= 1) s += __shfl_down_sync(0xffffffffu, s, o);
    if (lane == 0) g_cvec[i * 256 + j] = s + g_b1s[i * 256 + j];
}

__global__ void k_rc(const float* __restrict__ rel) {
    int gw = (blockIdx.x * blockDim.x + threadIdx.x) >> 5;
    int lane = threadIdx.x & 31;
    if (gw >= NSAMP * NRELC * 256) return;
    int j = gw & 255;
    int ir = gw >> 8;
    int r = ir % NRELC, i = ir / NRELC;
    const float* wrow = &g_w1s[((size_t)i * 256 + j) * PREDIN + 522];
    const float* rrow = &rel[(size_t)r * 256];
    float s = 0.0f;
    for (int c = lane; c < 256; c += 32) s += rrow[c] * wrow[c];
    for (int o = 16; o; o >>= 1) s += __shfl_down_sync(0xffffffffu, s, o);
    if (lane == 0) g_Rc[gw] = s + g_cvec[i * 256 + j];
}

// ---------------- fp16 tensor-core GEMM, cp.async double-buffered ----------------
// C[NP x 2560] = ext[NP x 288] * Wcat[2560 x 288]^T ; no bounds checks (padded)
#define BM 128
#define BN 128
#define BK 32
#define NKITER 9          // 288 / 32
#define LDSS 40           // smem row stride in halves (32 + 8 pad; 80B)
__global__ void __launch_bounds__(256) k_gemm_f16() {
    __shared__ __half As[2][BM * LDSS];
    __shared__ __half Bs[2][BN * LDSS];
    int bm = blockIdx.y * BM, bn = blockIdx.x * BN;
    int tid = threadIdx.x;
    int wid = tid >> 5, lane = tid & 31;
    int warp_m = wid >> 2;    // 0..1
    int warp_n = wid & 3;     // 0..3
    int lr = lane >> 2;       // 0..7
    int lc = lane & 3;        // 0..3

    float acc[4][4][4];
#pragma unroll
    for (int mt = 0; mt < 4; mt++)
#pragma unroll
        for (int nt = 0; nt < 4; nt++)
#pragma unroll
            for (int c = 0; c < 4; c++) acc[mt][nt][c] = 0.0f;

    int c0 = tid;               // chunk ids c0, c0+256

#define LOAD_STAGE(st, k0)                                                          \
    {                                                                               \
        _Pragma("unroll")                                                           \
        for (int q = 0; q < 2; q++) {                                               \
            int c = c0 + q * 256;                                                   \
            int row = c >> 2, seg = c & 3;                                          \
            cp16(&As[st][row * LDSS + seg * 8],                                     \
                 &g_ext[(size_t)(bm + row) * KPAD + (k0) + seg * 8]);               \
            cp16(&Bs[st][row * LDSS + seg * 8],                                     \
                 &g_Wcat[(size_t)(bn + row) * KPAD + (k0) + seg * 8]);              \
        }                                                                           \
    }

    LOAD_STAGE(0, 0);
    CP_COMMIT();

    int a_lrow = lane & 15;         // ldmatrix row-in-tile
    int a_koff = (lane >> 4) * 8;   // 0 or 8 halves

    for (int kb = 0; kb < NKITER; kb++) {
        if (kb + 1 < NKITER) {
            LOAD_STAGE((kb + 1) & 1, (kb + 1) * BK);
            CP_COMMIT();
            CP_WAIT(1);
        } else {
            CP_WAIT(0);
        }
        __syncthreads();
        const __half* as = As[kb & 1];
        const __half* bs = Bs[kb & 1];
#pragma unroll
        for (int s = 0; s < 2; s++) {
            int kh = s * 16;
            uint32_t af[4][4];
#pragma unroll
            for (int mt = 0; mt < 4; mt++) {
                int m0 = warp_m * 64 + mt * 16;
                ldsm_x4(af[mt], &as[(m0 + a_lrow) * LDSS + kh + a_koff]);
            }
            uint32_t bf[2][4];
#pragma unroll
            for (int np = 0; np < 2; np++) {
                int n0 = warp_n * 32 + np * 16;
                ldsm_x4(bf[np], &bs[(n0 + a_lrow) * LDSS + kh + a_koff]);
            }
#pragma unroll
            for (int mt = 0; mt < 4; mt++) {
#pragma unroll
                for (int nt = 0; nt < 4; nt++) {
                    uint32_t bb[2];
                    bb[0] = bf[nt >> 1][nt & 1];
                    bb[1] = bf[nt >> 1][2 + (nt & 1)];
                    mma_f16(acc[mt][nt], af[mt], bb);
                }
            }
        }
        __syncthreads();
    }

    // store fp16 to split g_A / g_B (padded rows: no guards)
#pragma unroll
    for (int mt = 0; mt < 4; mt++) {
#pragma unroll
        for (int nt = 0; nt < 4; nt++) {
            int col = bn + warp_n * 32 + nt * 8 + lc * 2;
            int i = col >> 9;
            int jj = col & 511;
            int gr0 = bm + warp_m * 64 + mt * 16 + lr;
            int gr1 = gr0 + 8;
            __half2 v0 = __floats2half2_rn(acc[mt][nt][0], acc[mt][nt][1]);
            __half2 v1 = __floats2half2_rn(acc[mt][nt][2], acc[mt][nt][3]);
            if (jj < 256) {
                *(__half2*)(&g_A[(size_t)gr0 * NODEW + i * 256 + jj]) = v0;
                *(__half2*)(&g_A[(size_t)gr1 * NODEW + i * 256 + jj]) = v1;
            } else {
                *(__half2*)(&g_B[(size_t)gr0 * NODEW + i * 256 + jj - 256]) = v0;
                *(__half2*)(&g_B[(size_t)gr1 * NODEW + i * 256 + jj - 256]) = v1;
            }
        }
    }
}

__global__ void k_b2sum() {
    if (threadIdx.x == 0) {
        float s = 0.0f;
#pragma unroll
        for (int i = 0; i < NSAMP; i++) s += g_b2s[i];
        g_b2sum_buf[0] = s;
    }
}

// warp per edge; contiguous fp16 A/B rows: lane loads one uint4 per sample per side
__global__ void __launch_bounds__(256) k_edge2(const int* __restrict__ h_id,
                                               const int* __restrict__ t_id,
                                               const int* __restrict__ r_id,
                                               float* __restrict__ out) {
    int gw = (blockIdx.x * blockDim.x + threadIdx.x) >> 5;
    int lane = threadIdx.x & 31;
    if (gw >= EE) return;
    int h = h_id[gw], t = t_id[gw], r = r_id[gw];
    const __half* ah = &g_A[(size_t)h * NODEW];
    const __half* bt = &g_B[(size_t)t * NODEW];
    const float4* rc = (const float4*)&g_Rc[(size_t)r * 256];
    const float4* w2 = (const float4*)g_w2s;
    float acc = 0.0f;
#pragma unroll
    for (int i = 0; i < NSAMP; i++) {
        uint4 a4 = *(const uint4*)(ah + i * 256 + lane * 8);
        uint4 b4 = *(const uint4*)(bt + i * 256 + lane * 8);
        const float4* rci = rc + (size_t)i * (NRELC * 64);
        const float4* w2i = w2 + i * 64;
        float4 c0 = rci[lane * 2], c1 = rci[lane * 2 + 1];
        float4 w0 = w2i[lane * 2], w1 = w2i[lane * 2 + 1];
        const __half2* a2 = (const __half2*)&a4;
        const __half2* b2 = (const __half2*)&b4;
        float2 af0 = __half22float2(a2[0]), bf0 = __half22float2(b2[0]);
        float2 af1 = __half22float2(a2[1]), bf1 = __half22float2(b2[1]);
        float2 af2 = __half22float2(a2[2]), bf2 = __half22float2(b2[2]);
        float2 af3 = __half22float2(a2[3]), bf3 = __half22float2(b2[3]);
        acc = fmaf(fmaxf(af0.x + bf0.x + c0.x, 0.0f), w0.x, acc);
        acc = fmaf(fmaxf(af0.y + bf0.y + c0.y, 0.0f), w0.y, acc);
        acc = fmaf(fmaxf(af1.x + bf1.x + c0.z, 0.0f), w0.z, acc);
        acc = fmaf(fmaxf(af1.y + bf1.y + c0.w, 0.0f), w0.w, acc);
        acc = fmaf(fmaxf(af2.x + bf2.x + c1.x, 0.0f), w1.x, acc);
        acc = fmaf(fmaxf(af2.y + bf2.y + c1.y, 0.0f), w1.y, acc);
        acc = fmaf(fmaxf(af3.x + bf3.x + c1.z, 0.0f), w1.z, acc);
        acc = fmaf(fmaxf(af3.y + bf3.y + c1.w, 0.0f), w1.w, acc);
    }
    for (int o = 16; o; o >>= 1) acc += __shfl_down_sync(0xffffffffu, acc, o);
    if (lane == 0) out[gw] = (acc + g_b2sum_buf[0]) * 0.2f;
}

// ---------------- host ----------------
extern "C" void kernel_launch(void* const* d_in, const int* in_sizes, int n_in,
                              void* d_out, int out_size) {
    int sh = (n_in >= 17) ? 0 : -1;
    const int*   h_id   = (const int*)d_in[0];
    const int*   r_id   = (const int*)d_in[1];
    const int*   t_id   = (const int*)d_in[2];
    const float* q_emb  = (const float*)d_in[3];
    const float* ent    = (const float*)d_in[4];
    const float* rel    = (const float*)d_in[6 + sh];
    const float* topic  = (const float*)d_in[7 + sh];
    const float* nontxt = (const float*)d_in[8 + sh];
    const float* w1mu   = (const float*)d_in[9 + sh];
    const float* w1rho  = (const float*)d_in[10 + sh];
    const float* b1mu   = (const float*)d_in[11 + sh];
    const float* b1rho  = (const float*)d_in[12 + sh];
    const float* w2mu   = (const float*)d_in[13 + sh];
    const float* w2rho  = (const float*)d_in[14 + sh];
    const float* b2mu   = (const float*)d_in[15 + sh];
    const float* b2rho  = (const float*)d_in[16 + sh];
    float* out = (float*)d_out;

    // JAX keys (threefry_partitionable=True)
    Keys K;
    for (int i = 0; i < NSAMP; i++) {
        unsigned f0, f1;
        tf2x32(0u, 42u, 0u, (unsigned)i, f0, f1);
        for (int jj = 0; jj < 4; jj++) {
            unsigned a, b;
            tf2x32(f0, f1, 0u, (unsigned)jj, a, b);
            K.k[i][jj][0] = a; K.k[i][jj][1] = b;
        }
    }

    const int T = 256;
    // graph features
    k_zero<<<(NN * 2 + T - 1) / T, T>>>();
    k_scat1<<<(EE + T - 1) / T, T>>>(h_id, t_id, topic);
    {
        long long tot = (long long)NP * KPAD;
        k_build1<<<(unsigned)((tot + T - 1) / T), T>>>(ent, nontxt, topic);
    }
    k_scat2<<<(EE + T - 1) / T, T>>>(h_id, t_id);
    k_fill2<<<(NN * 2 + T - 1) / T, T>>>();

    // weight sampling (partitionable threefry)
    {
        dim3 g((W1FLAT + 513 + T - 1) / T, NSAMP);
        k_sample<<<g, T>>>(K, w1mu, w1rho, b1mu, b1rho, w2mu, w2rho, b2mu, b2rho);
    }
    {
        long long tot = (long long)CAB * KPAD;
        k_build_wcat<<<(unsigned)((tot + T - 1) / T), T>>>();
    }
    k_cvec<<<(NSAMP * 256 * 32 + T - 1) / T, T>>>(q_emb);
    k_rc<<<(NSAMP * NRELC * 256 * 32 + T - 1) / T, T>>>(rel);
    k_b2sum<<<1, 32>>>();

    // big GEMM: [100096 x 288] x [2560 x 288]^T (fp16 mma.sync, cp.async pipeline)
    {
        dim3 g(CAB / BN, NP / BM);
        k_gemm_f16<<<g, 256>>>();
    }

    // edge stage: warp per edge
    {
        long long threads = (long long)EE * 32;
        k_edge2<<<(unsigned)((threads + T - 1) / T), T>>>(h_id, t_id, r_id, out);
    }
}

// round 14
// speedup vs baseline: 3.4983x; 1.1220x over previous
#include <cuda_runtime.h>
#include <cuda_fp16.h>
#include <cstdint>

// ---------------- problem constants ----------------
#define EE      500000
#define NN      100000
#define NP      100096   // NN padded to /128 (guard-free GEMM tiles)
#define NTEXT   90000
#define NRELC   500
#define KE      266
#define KPAD    288      // K padded to /32 (9 x BK)
#define NSAMP   5
#define PREDIN  1044
#define W1FLAT  267264   // 256*1044
#define CAB     2560     // 5 samples * (256 A + 256 B)
#define NODEW   1280     // per-node halves in g_A / g_B

// ---------------- device scratch (static, allowed) ----------------
__device__ __half g_ext[(size_t)NP * KPAD];
__device__ __half g_A[(size_t)NP * NODEW];
__device__ __half g_B[(size_t)NP * NODEW];
__device__ __half g_Wcat[(size_t)CAB * KPAD];
__device__ float g_w1s[(size_t)NSAMP * W1FLAT];
__device__ float g_b1s[NSAMP * 256];
__device__ float g_w2s[NSAMP * 256];
__device__ float g_b2s[NSAMP];
__device__ float g_cvec[NSAMP * 256];
__device__ __half g_Rc_h[(size_t)NSAMP * NRELC * 256];  // fp16 Rc (halve L2 traffic)
__device__ float g_sumA[NN * 2];
__device__ float g_sumB[NN * 2];
__device__ float g_degT[NN];
__device__ float g_degH[NN];
__device__ float g_b2sum_buf[1];

struct Keys { unsigned int k[NSAMP][4][2]; };

// ---------------- threefry2x32 (JAX-exact) ----------------
__host__ __device__ __forceinline__ unsigned int rotl32(unsigned int x, int r) {
    return (x << r) | (x >> (32 - r));
}
__host__ __device__ __forceinline__ void tf2x32(unsigned int k0, unsigned int k1,
                                                unsigned int x0, unsigned int x1,
                                                unsigned int& o0, unsigned int& o1) {
    unsigned int ks2 = k0 ^ k1 ^ 0x1BD11BDAu;
    x0 += k0; x1 += k1;
#define TFR(r) { x0 += x1; x1 = rotl32(x1, r); x1 ^= x0; }
    TFR(13) TFR(15) TFR(26) TFR(6)   x0 += k1;  x1 += ks2 + 1u;
    TFR(17) TFR(29) TFR(16) TFR(24)  x0 += ks2; x1 += k0 + 2u;
    TFR(13) TFR(15) TFR(26) TFR(6)   x0 += k0;  x1 += k1 + 3u;
    TFR(17) TFR(29) TFR(16) TFR(24)  x0 += k1;  x1 += ks2 + 4u;
    TFR(13) TFR(15) TFR(26) TFR(6)   x0 += ks2; x1 += k0 + 5u;
#undef TFR
    o0 = x0; o1 = x1;
}

// XLA f32 ErfInv (Giles polynomial)
__device__ __forceinline__ float erfinv_f32(float x) {
    float w = -log1pf(-x * x);
    float p;
    if (w < 5.0f) {
        w -= 2.5f;
        p = 2.81022636e-08f;
        p = fmaf(p, w, 3.43273939e-07f);
        p = fmaf(p, w, -3.5233877e-06f);
        p = fmaf(p, w, -4.39150654e-06f);
        p = fmaf(p, w, 0.00021858087f);
        p = fmaf(p, w, -0.00125372503f);
        p = fmaf(p, w, -0.00417768164f);
        p = fmaf(p, w, 0.246640727f);
        p = fmaf(p, w, 1.50140941f);
    } else {
        w = sqrtf(w) - 3.0f;
        p = -0.000200214257f;
        p = fmaf(p, w, 0.000100950558f);
        p = fmaf(p, w, 0.00134934322f);
        p = fmaf(p, w, -0.00367342844f);
        p = fmaf(p, w, 0.00573950773f);
        p = fmaf(p, w, -0.0076224613f);
        p = fmaf(p, w, 0.00943887047f);
        p = fmaf(p, w, 1.00167406f);
        p = fmaf(p, w, 2.83297682f);
    }
    return p * x;
}

__device__ __forceinline__ float bits_to_normal(unsigned int b) {
    float f01 = __uint_as_float((b >> 9) | 0x3f800000u) - 1.0f;
    float u = __fadd_rn(__fmul_rn(f01, 2.0f), -0.99999994f);
    u = fmaxf(-0.99999994f, u);
    return __fmul_rn(1.41421356237f, erfinv_f32(u));
}

__device__ __forceinline__ float softplusf(float x) {
    return fmaxf(x, 0.0f) + log1pf(expf(-fabsf(x)));
}

__device__ __forceinline__ void mma_f16(float* c, const uint32_t* a, const uint32_t* b) {
    asm volatile(
        "mma.sync.aligned.m16n8k16.row.col.f32.f16.f16.f32 "
        "{%0,%1,%2,%3}, {%4,%5,%6,%7}, {%8,%9}, {%0,%1,%2,%3};\n"
        : "+f"(c[0]), "+f"(c[1]), "+f"(c[2]), "+f"(c[3])
        : "r"(a[0]), "r"(a[1]), "r"(a[2]), "r"(a[3]), "r"(b[0]), "r"(b[1]));
}

__device__ __forceinline__ void ldsm_x4(uint32_t* r, const void* sptr) {
    uint32_t a = (uint32_t)__cvta_generic_to_shared(sptr);
    asm volatile("ldmatrix.sync.aligned.m8n8.x4.shared.b16 {%0,%1,%2,%3}, [%4];"
                 : "=r"(r[0]), "=r"(r[1]), "=r"(r[2]), "=r"(r[3]) : "r"(a));
}

__device__ __forceinline__ void cp16(const void* sdst, const void* gsrc) {
    uint32_t d = (uint32_t)__cvta_generic_to_shared(sdst);
    asm volatile("cp.async.cg.shared.global [%0], [%1], 16;\n" :: "r"(d), "l"(gsrc));
}
#define CP_COMMIT() asm volatile("cp.async.commit_group;\n")
#define CP_WAIT(n)  asm volatile("cp.async.wait_group %0;\n" :: "n"(n))

// ---------------- graph-feature kernels ----------------
__global__ void k_zero() {
    int i = blockIdx.x * blockDim.x + threadIdx.x;
    if (i < NN * 2) { g_sumA[i] = 0.0f; g_sumB[i] = 0.0f; }
    if (i < NN)     { g_degT[i] = 0.0f; g_degH[i] = 0.0f; }
}

__global__ void k_scat1(const int* __restrict__ h_id, const int* __restrict__ t_id,
                        const float* __restrict__ topic) {
    int e = blockIdx.x * blockDim.x + threadIdx.x;
    if (e >= EE) return;
    int h = h_id[e], t = t_id[e];
    float x0 = topic[h * 2], x1 = topic[h * 2 + 1];
    atomicAdd(&g_sumA[t * 2], x0); atomicAdd(&g_sumA[t * 2 + 1], x1);
    float y0 = topic[t * 2], y1 = topic[t * 2 + 1];
    atomicAdd(&g_sumB[h * 2], y0); atomicAdd(&g_sumB[h * 2 + 1], y1);
    atomicAdd(&g_degT[t], 1.0f);
    atomicAdd(&g_degH[h], 1.0f);
}

__global__ void k_build1(const float* __restrict__ ent, const float* __restrict__ nontext,
                         const float* __restrict__ topic) {
    long long idx = (long long)blockIdx.x * blockDim.x + threadIdx.x;
    if (idx >= (long long)NP * KPAD) return;
    int n = (int)(idx / KPAD), c = (int)(idx % KPAD);
    float v = 0.0f;
    if (n < NN) {
        if (c < 256) {
            v = (n < NTEXT) ? ent[(size_t)n * 256 + c] : nontext[c];
        } else if (c < 258) {
            v = topic[n * 2 + (c - 256)];
        } else if (c < 260) {
            int k = c - 258;
            v = g_sumA[n * 2 + k] / fmaxf(g_degT[n], 1.0f);
            g_sumA[n * 2 + k] = 0.0f;
        } else if (c >= 262 && c < 264) {
            int k = c - 262;
            v = g_sumB[n * 2 + k] / fmaxf(g_degH[n], 1.0f);
            g_sumB[n * 2 + k] = 0.0f;
        }
    }
    g_ext[(size_t)n * KPAD + c] = __float2half_rn(v);
}

__global__ void k_scat2(const int* __restrict__ h_id, const int* __restrict__ t_id) {
    int e = blockIdx.x * blockDim.x + threadIdx.x;
    if (e >= EE) return;
    int h = h_id[e], t = t_id[e];
    float a0 = __half2float(g_ext[(size_t)h * KPAD + 258]);
    float a1 = __half2float(g_ext[(size_t)h * KPAD + 259]);
    atomicAdd(&g_sumA[t * 2], a0); atomicAdd(&g_sumA[t * 2 + 1], a1);
    float b0 = __half2float(g_ext[(size_t)t * KPAD + 262]);
    float b1v = __half2float(g_ext[(size_t)t * KPAD + 263]);
    atomicAdd(&g_sumB[h * 2], b0); atomicAdd(&g_sumB[h * 2 + 1], b1v);
}

__global__ void k_fill2() {
    int idx = blockIdx.x * blockDim.x + threadIdx.x;
    if (idx >= NN * 2) return;
    int n = idx >> 1, k = idx & 1;
    g_ext[(size_t)n * KPAD + 260 + k] = __float2half_rn(g_sumA[n * 2 + k] / fmaxf(g_degT[n], 1.0f));
    g_ext[(size_t)n * KPAD + 264 + k] = __float2half_rn(g_sumB[n * 2 + k] / fmaxf(g_degH[n], 1.0f));
}

// PARTITIONABLE threefry (JAX >= 0.4.30 default)
__global__ void k_sample(Keys K,
                         const float* __restrict__ w1mu, const float* __restrict__ w1rho,
                         const float* __restrict__ b1mu, const float* __restrict__ b1rho,
                         const float* __restrict__ w2mu, const float* __restrict__ w2rho,
                         const float* __restrict__ b2mu, const float* __restrict__ b2rho) {
    int i = blockIdx.y;
    int j = blockIdx.x * blockDim.x + threadIdx.x;
    unsigned int v0, v1;
    if (j < W1FLAT) {
        tf2x32(K.k[i][0][0], K.k[i][0][1], 0u, (unsigned)j, v0, v1);
        float z = bits_to_normal(v0 ^ v1);
        g_w1s[(size_t)i * W1FLAT + j] = w1mu[j] + z * softplusf(w1rho[j]);
    } else if (j < W1FLAT + 256) {
        int jj = j - W1FLAT;
        tf2x32(K.k[i][1][0], K.k[i][1][1], 0u, (unsigned)jj, v0, v1);
        g_b1s[i * 256 + jj] = b1mu[jj] + bits_to_normal(v0 ^ v1) * softplusf(b1rho[jj]);
    } else if (j < W1FLAT + 512) {
        int jj = j - W1FLAT - 256;
        tf2x32(K.k[i][2][0], K.k[i][2][1], 0u, (unsigned)jj, v0, v1);
        g_w2s[i * 256 + jj] = w2mu[jj] + bits_to_normal(v0 ^ v1) * softplusf(w2rho[jj]);
    } else if (j == W1FLAT + 512) {
        tf2x32(K.k[i][3][0], K.k[i][3][1], 0u, 0u, v0, v1);
        g_b2s[i] = b2mu[0] + bits_to_normal(v0 ^ v1) * softplusf(b2rho[0]);
    }
}

__global__ void k_build_wcat() {
    long long idx = (long long)blockIdx.x * blockDim.x + threadIdx.x;
    if (idx >= (long long)CAB * KPAD) return;
    int n = (int)(idx / KPAD), c = (int)(idx % KPAD);
    float v = 0.0f;
    if (c < KE) {
        int i = n >> 9, jj = n & 511;
        int row = (jj < 256) ? jj : (jj - 256);
        int off = (jj < 256) ? 256 : 778;
        v = g_w1s[((size_t)i * 256 + row) * PREDIN + off + c];
    }
    g_Wcat[idx] = __float2half_rn(v);
}

__global__ void k_cvec(const float* __restrict__ q) {
    int gw = (blockIdx.x * blockDim.x + threadIdx.x) >> 5;
    int lane = threadIdx.x & 31;
    if (gw >= NSAMP * 256) return;
    int i = gw >> 8, j = gw & 255;
    const float* wrow = &g_w1s[((size_t)i * 256 + j) * PREDIN];
    float s = 0.0f;
    for (int c = lane; c < 256; c += 32) s += q[c] * wrow[c];
    for (int o = 16; o; o >>= 1) s += __shfl_down_sync(0xffffffffu, s, o);
    if (lane == 0) g_cvec[i * 256 + j] = s + g_b1s[i * 256 + j];
}

// Rc as tiled GEMM: Rc[i][r][j] = rel[r] . w1[i][j][522:778] + cvec[i][j]  (fp16 out)
// grid (4 j-tiles, 8 r-tiles, 5 samples); block 256; 64x64 tile, BK=16
__global__ void __launch_bounds__(256) k_rc2(const float* __restrict__ rel) {
    __shared__ float Rs[16][68];
    __shared__ float Ws[16][68];
    int jt = blockIdx.x * 64, rt = blockIdx.y * 64, i = blockIdx.z;
    int tid = threadIdx.x;
    int lrw = tid >> 2;          // 0..63
    int cseg = (tid & 3) * 4;    // 0,4,8,12
    int tx = tid & 15, ty = tid >> 4;
    int j0 = tx * 4, r0 = ty * 4;

    float acc[4][4];
#pragma unroll
    for (int x = 0; x < 4; x++)
#pragma unroll
        for (int y = 0; y < 4; y++) acc[x][y] = 0.0f;

    for (int c0 = 0; c0 < 256; c0 += 16) {
        float4 rv = make_float4(0.f, 0.f, 0.f, 0.f);
        if (rt + lrw < NRELC)
            rv = *(const float4*)(&rel[(size_t)(rt + lrw) * 256 + c0 + cseg]);
        Rs[cseg][lrw] = rv.x; Rs[cseg + 1][lrw] = rv.y;
        Rs[cseg + 2][lrw] = rv.z; Rs[cseg + 3][lrw] = rv.w;
        const float* wp = &g_w1s[((size_t)i * 256 + jt + lrw) * PREDIN + 522 + c0 + cseg];
        float2 w0 = *(const float2*)(wp);
        float2 w1v = *(const float2*)(wp + 2);
        Ws[cseg][lrw] = w0.x; Ws[cseg + 1][lrw] = w0.y;
        Ws[cseg + 2][lrw] = w1v.x; Ws[cseg + 3][lrw] = w1v.y;
        __syncthreads();
#pragma unroll
        for (int k = 0; k < 16; k++) {
            float ra[4], wb[4];
#pragma unroll
            for (int x = 0; x < 4; x++) { ra[x] = Rs[k][r0 + x]; wb[x] = Ws[k][j0 + x]; }
#pragma unroll
            for (int x = 0; x < 4; x++)
#pragma unroll
                for (int y = 0; y < 4; y++) acc[x][y] = fmaf(ra[x], wb[y], acc[x][y]);
        }
        __syncthreads();
    }
#pragma unroll
    for (int x = 0; x < 4; x++) {
        int r = rt + r0 + x;
        if (r < NRELC) {
#pragma unroll
            for (int y = 0; y < 4; y++) {
                int j = jt + j0 + y;
                g_Rc_h[((size_t)i * NRELC + r) * 256 + j] =
                    __float2half_rn(acc[x][y] + g_cvec[i * 256 + j]);
            }
        }
    }
}

// ---------------- fp16 tensor-core GEMM, cp.async double-buffered (1 barrier/iter) --
#define BM 128
#define BN 128
#define BK 32
#define NKITER 9
#define LDSS 40
__global__ void __launch_bounds__(256) k_gemm_f16() {
    __shared__ __half As[2][BM * LDSS];
    __shared__ __half Bs[2][BN * LDSS];
    int bm = blockIdx.y * BM, bn = blockIdx.x * BN;
    int tid = threadIdx.x;
    int wid = tid >> 5, lane = tid & 31;
    int warp_m = wid >> 2;
    int warp_n = wid & 3;
    int lr = lane >> 2;
    int lc = lane & 3;

    float acc[4][4][4];
#pragma unroll
    for (int mt = 0; mt < 4; mt++)
#pragma unroll
        for (int nt = 0; nt < 4; nt++)
#pragma unroll
            for (int c = 0; c < 4; c++) acc[mt][nt][c] = 0.0f;

    int c0 = tid;

#define LOAD_STAGE(st, k0)                                                          \
    {                                                                               \
        _Pragma("unroll")                                                           \
        for (int q = 0; q < 2; q++) {                                               \
            int c = c0 + q * 256;                                                   \
            int row = c >> 2, seg = c & 3;                                          \
            cp16(&As[st][row * LDSS + seg * 8],                                     \
                 &g_ext[(size_t)(bm + row) * KPAD + (k0) + seg * 8]);               \
            cp16(&Bs[st][row * LDSS + seg * 8],                                     \
                 &g_Wcat[(size_t)(bn + row) * KPAD + (k0) + seg * 8]);              \
        }                                                                           \
    }

    LOAD_STAGE(0, 0);
    CP_COMMIT();

    int a_lrow = lane & 15;
    int a_koff = (lane >> 4) * 8;

    for (int kb = 0; kb < NKITER; kb++) {
        CP_WAIT(0);
        __syncthreads();   // stage kb visible to all; compute(kb-1) retired everywhere
        if (kb + 1 < NKITER) {
            LOAD_STAGE((kb + 1) & 1, (kb + 1) * BK);
            CP_COMMIT();
        }
        const __half* as = As[kb & 1];
        const __half* bs = Bs[kb & 1];
#pragma unroll
        for (int s = 0; s < 2; s++) {
            int kh = s * 16;
            uint32_t af[4][4];
#pragma unroll
            for (int mt = 0; mt < 4; mt++) {
                int m0 = warp_m * 64 + mt * 16;
                ldsm_x4(af[mt], &as[(m0 + a_lrow) * LDSS + kh + a_koff]);
            }
            uint32_t bf[2][4];
#pragma unroll
            for (int np = 0; np < 2; np++) {
                int n0 = warp_n * 32 + np * 16;
                ldsm_x4(bf[np], &bs[(n0 + a_lrow) * LDSS + kh + a_koff]);
            }
#pragma unroll
            for (int mt = 0; mt < 4; mt++) {
#pragma unroll
                for (int nt = 0; nt < 4; nt++) {
                    uint32_t bb[2];
                    bb[0] = bf[nt >> 1][nt & 1];
                    bb[1] = bf[nt >> 1][2 + (nt & 1)];
                    mma_f16(acc[mt][nt], af[mt], bb);
                }
            }
        }
    }

#pragma unroll
    for (int mt = 0; mt < 4; mt++) {
#pragma unroll
        for (int nt = 0; nt < 4; nt++) {
            int col = bn + warp_n * 32 + nt * 8 + lc * 2;
            int i = col >> 9;
            int jj = col & 511;
            int gr0 = bm + warp_m * 64 + mt * 16 + lr;
            int gr1 = gr0 + 8;
            __half2 v0 = __floats2half2_rn(acc[mt][nt][0], acc[mt][nt][1]);
            __half2 v1 = __floats2half2_rn(acc[mt][nt][2], acc[mt][nt][3]);
            if (jj < 256) {
                *(__half2*)(&g_A[(size_t)gr0 * NODEW + i * 256 + jj]) = v0;
                *(__half2*)(&g_A[(size_t)gr1 * NODEW + i * 256 + jj]) = v1;
            } else {
                *(__half2*)(&g_B[(size_t)gr0 * NODEW + i * 256 + jj - 256]) = v0;
                *(__half2*)(&g_B[(size_t)gr1 * NODEW + i * 256 + jj - 256]) = v1;
            }
        }
    }
}

__global__ void k_b2sum() {
    if (threadIdx.x == 0) {
        float s = 0.0f;
#pragma unroll
        for (int i = 0; i < NSAMP; i++) s += g_b2s[i];
        g_b2sum_buf[0] = s;
    }
}

// warp per edge; w2 in smem, Rc fp16; per lane: uint4 A + uint4 B + uint4 Rc per sample
__global__ void __launch_bounds__(256) k_edge3(const int* __restrict__ h_id,
                                               const int* __restrict__ t_id,
                                               const int* __restrict__ r_id,
                                               float* __restrict__ out) {
    __shared__ float sw2[NSAMP * 256];
    __shared__ float sb2;
    int tid = threadIdx.x;
    for (int idx = tid; idx < NSAMP * 256; idx += 256) sw2[idx] = g_w2s[idx];
    if (tid == 0) sb2 = g_b2sum_buf[0];
    __syncthreads();

    int gw = (blockIdx.x * blockDim.x + tid) >> 5;
    int lane = tid & 31;
    if (gw >= EE) return;
    int h = h_id[gw], t = t_id[gw], r = r_id[gw];
    const __half* ah = &g_A[(size_t)h * NODEW];
    const __half* bt = &g_B[(size_t)t * NODEW];
    const __half* rc = &g_Rc_h[(size_t)r * 256];
    float acc = 0.0f;
#pragma unroll
    for (int i = 0; i < NSAMP; i++) {
        uint4 a4 = *(const uint4*)(ah + i * 256 + lane * 8);
        uint4 b4 = *(const uint4*)(bt + i * 256 + lane * 8);
        uint4 c4 = *(const uint4*)(rc + (size_t)i * (NRELC * 256) + lane * 8);
        const float4* w2i = (const float4*)&sw2[i * 256];
        float4 w0 = w2i[lane * 2], w1 = w2i[lane * 2 + 1];
        const __half2* a2 = (const __half2*)&a4;
        const __half2* b2 = (const __half2*)&b4;
        const __half2* c2 = (const __half2*)&c4;
#pragma unroll
        for (int p = 0; p < 4; p++) {
            float2 af = __half22float2(a2[p]);
            float2 bf = __half22float2(b2[p]);
            float2 cf = __half22float2(c2[p]);
            float wx = (p < 2) ? ((p == 0) ? w0.x : w0.z) : ((p == 2) ? w1.x : w1.z);
            float wy = (p < 2) ? ((p == 0) ? w0.y : w0.w) : ((p == 2) ? w1.y : w1.w);
            acc = fmaf(fmaxf(af.x + bf.x + cf.x, 0.0f), wx, acc);
            acc = fmaf(fmaxf(af.y + bf.y + cf.y, 0.0f), wy, acc);
        }
    }
    for (int o = 16; o; o >>= 1) acc += __shfl_down_sync(0xffffffffu, acc, o);
    if (lane == 0) out[gw] = (acc + sb2) * 0.2f;
}

// ---------------- host ----------------
extern "C" void kernel_launch(void* const* d_in, const int* in_sizes, int n_in,
                              void* d_out, int out_size) {
    int sh = (n_in >= 17) ? 0 : -1;
    const int*   h_id   = (const int*)d_in[0];
    const int*   r_id   = (const int*)d_in[1];
    const int*   t_id   = (const int*)d_in[2];
    const float* q_emb  = (const float*)d_in[3];
    const float* ent    = (const float*)d_in[4];
    const float* rel    = (const float*)d_in[6 + sh];
    const float* topic  = (const float*)d_in[7 + sh];
    const float* nontxt = (const float*)d_in[8 + sh];
    const float* w1mu   = (const float*)d_in[9 + sh];
    const float* w1rho  = (const float*)d_in[10 + sh];
    const float* b1mu   = (const float*)d_in[11 + sh];
    const float* b1rho  = (const float*)d_in[12 + sh];
    const float* w2mu   = (const float*)d_in[13 + sh];
    const float* w2rho  = (const float*)d_in[14 + sh];
    const float* b2mu   = (const float*)d_in[15 + sh];
    const float* b2rho  = (const float*)d_in[16 + sh];
    float* out = (float*)d_out;

    // JAX keys (threefry_partitionable=True)
    Keys K;
    for (int i = 0; i < NSAMP; i++) {
        unsigned f0, f1;
        tf2x32(0u, 42u, 0u, (unsigned)i, f0, f1);
        for (int jj = 0; jj < 4; jj++) {
            unsigned a, b;
            tf2x32(f0, f1, 0u, (unsigned)jj, a, b);
            K.k[i][jj][0] = a; K.k[i][jj][1] = b;
        }
    }

    const int T = 256;
    // graph features
    k_zero<<<(NN * 2 + T - 1) / T, T>>>();
    k_scat1<<<(EE + T - 1) / T, T>>>(h_id, t_id, topic);
    {
        long long tot = (long long)NP * KPAD;
        k_build1<<<(unsigned)((tot + T - 1) / T), T>>>(ent, nontxt, topic);
    }
    k_scat2<<<(EE + T - 1) / T, T>>>(h_id, t_id);
    k_fill2<<<(NN * 2 + T - 1) / T, T>>>();

    // weight sampling (partitionable threefry)
    {
        dim3 g((W1FLAT + 513 + T - 1) / T, NSAMP);
        k_sample<<<g, T>>>(K, w1mu, w1rho, b1mu, b1rho, w2mu, w2rho, b2mu, b2rho);
    }
    {
        long long tot = (long long)CAB * KPAD;
        k_build_wcat<<<(unsigned)((tot + T - 1) / T), T>>>();
    }
    k_cvec<<<(NSAMP * 256 * 32 + T - 1) / T, T>>>(q_emb);
    {
        dim3 g(4, 8, NSAMP);   // 256/64 j-tiles, ceil(500/64) r-tiles, samples
        k_rc2<<<g, 256>>>(rel);
    }
    k_b2sum<<<1, 32>>>();

    // big GEMM: [100096 x 288] x [2560 x 288]^T (fp16 mma.sync, cp.async pipeline)
    {
        dim3 g(CAB / BN, NP / BM);
        k_gemm_f16<<<g, 256>>>();
    }

    // edge stage: warp per edge
    {
        long long threads = (long long)EE * 32;
        k_edge3<<<(unsigned)((threads + T - 1) / T), T>>>(h_id, t_id, r_id, out);
    }
}

// round 15
// speedup vs baseline: 3.5028x; 1.0013x over previous
#include <cuda_runtime.h>
#include <cuda_fp16.h>
#include <cstdint>

// ---------------- problem constants ----------------
#define EE      500000
#define NN      100000
#define NP      100096   // NN padded to /128 (guard-free GEMM tiles)
#define NTEXT   90000
#define NRELC   500
#define KE      266
#define KPAD    288      // K padded to /32 (9 x BK)
#define NSAMP   5
#define PREDIN  1044
#define W1FLAT  267264   // 256*1044
#define CAB     2560
#define NODEW   1280     // per-node halves in g_A / g_B
#define NBSCAN  392      // 392*256 = 100352 >= NN

// ---------------- device scratch (static, allowed) ----------------
__device__ __half g_ext[(size_t)NP * KPAD];
__device__ __half g_A[(size_t)NP * NODEW];
__device__ __half g_B[(size_t)NP * NODEW];
__device__ __half g_Wcat[(size_t)CAB * KPAD];   // cols >= KE stay statically zero
__device__ float g_w1s[(size_t)NSAMP * W1FLAT];
__device__ float g_b1s[NSAMP * 256];
__device__ float g_w2s[NSAMP * 256];
__device__ float g_b2s[NSAMP];
__device__ float g_cvec[NSAMP * 256];
__device__ __half g_Rc_h[(size_t)NSAMP * NRELC * 256];
__device__ float g_sumA[NN * 2];
__device__ float g_sumB[NN * 2];
__device__ float g_degT[NN];
__device__ float g_degH[NN];
__device__ float g_b2sum_buf[1];
__device__ int   g_cnt[NN];       // histogram -> offsets
__device__ int   g_bsum[NBSCAN];  // scan block sums
__device__ int   g_perm[EE];      // edge ids sorted by h

struct Keys { unsigned int k[NSAMP][4][2]; };

// ---------------- threefry2x32 (JAX-exact) ----------------
__host__ __device__ __forceinline__ unsigned int rotl32(unsigned int x, int r) {
    return (x << r) | (x >> (32 - r));
}
__host__ __device__ __forceinline__ void tf2x32(unsigned int k0, unsigned int k1,
                                                unsigned int x0, unsigned int x1,
                                                unsigned int& o0, unsigned int& o1) {
    unsigned int ks2 = k0 ^ k1 ^ 0x1BD11BDAu;
    x0 += k0; x1 += k1;
#define TFR(r) { x0 += x1; x1 = rotl32(x1, r); x1 ^= x0; }
    TFR(13) TFR(15) TFR(26) TFR(6)   x0 += k1;  x1 += ks2 + 1u;
    TFR(17) TFR(29) TFR(16) TFR(24)  x0 += ks2; x1 += k0 + 2u;
    TFR(13) TFR(15) TFR(26) TFR(6)   x0 += k0;  x1 += k1 + 3u;
    TFR(17) TFR(29) TFR(16) TFR(24)  x0 += k1;  x1 += ks2 + 4u;
    TFR(13) TFR(15) TFR(26) TFR(6)   x0 += ks2; x1 += k0 + 5u;
#undef TFR
    o0 = x0; o1 = x1;
}

// XLA f32 ErfInv (Giles polynomial)
__device__ __forceinline__ float erfinv_f32(float x) {
    float w = -log1pf(-x * x);
    float p;
    if (w < 5.0f) {
        w -= 2.5f;
        p = 2.81022636e-08f;
        p = fmaf(p, w, 3.43273939e-07f);
        p = fmaf(p, w, -3.5233877e-06f);
        p = fmaf(p, w, -4.39150654e-06f);
        p = fmaf(p, w, 0.00021858087f);
        p = fmaf(p, w, -0.00125372503f);
        p = fmaf(p, w, -0.00417768164f);
        p = fmaf(p, w, 0.246640727f);
        p = fmaf(p, w, 1.50140941f);
    } else {
        w = sqrtf(w) - 3.0f;
        p = -0.000200214257f;
        p = fmaf(p, w, 0.000100950558f);
        p = fmaf(p, w, 0.00134934322f);
        p = fmaf(p, w, -0.00367342844f);
        p = fmaf(p, w, 0.00573950773f);
        p = fmaf(p, w, -0.0076224613f);
        p = fmaf(p, w, 0.00943887047f);
        p = fmaf(p, w, 1.00167406f);
        p = fmaf(p, w, 2.83297682f);
    }
    return p * x;
}

__device__ __forceinline__ float bits_to_normal(unsigned int b) {
    float f01 = __uint_as_float((b >> 9) | 0x3f800000u) - 1.0f;
    float u = __fadd_rn(__fmul_rn(f01, 2.0f), -0.99999994f);
    u = fmaxf(-0.99999994f, u);
    return __fmul_rn(1.41421356237f, erfinv_f32(u));
}

__device__ __forceinline__ float softplusf(float x) {
    return fmaxf(x, 0.0f) + log1pf(expf(-fabsf(x)));
}

__device__ __forceinline__ void mma_f16(float* c, const uint32_t* a, const uint32_t* b) {
    asm volatile(
        "mma.sync.aligned.m16n8k16.row.col.f32.f16.f16.f32 "
        "{%0,%1,%2,%3}, {%4,%5,%6,%7}, {%8,%9}, {%0,%1,%2,%3};\n"
        : "+f"(c[0]), "+f"(c[1]), "+f"(c[2]), "+f"(c[3])
        : "r"(a[0]), "r"(a[1]), "r"(a[2]), "r"(a[3]), "r"(b[0]), "r"(b[1]));
}

__device__ __forceinline__ void ldsm_x4(uint32_t* r, const void* sptr) {
    uint32_t a = (uint32_t)__cvta_generic_to_shared(sptr);
    asm volatile("ldmatrix.sync.aligned.m8n8.x4.shared.b16 {%0,%1,%2,%3}, [%4];"
                 : "=r"(r[0]), "=r"(r[1]), "=r"(r[2]), "=r"(r[3]) : "r"(a));
}

__device__ __forceinline__ void cp16(const void* sdst, const void* gsrc) {
    uint32_t d = (uint32_t)__cvta_generic_to_shared(sdst);
    asm volatile("cp.async.cg.shared.global [%0], [%1], 16;\n" :: "r"(d), "l"(gsrc));
}
#define CP_COMMIT() asm volatile("cp.async.commit_group;\n")
#define CP_WAIT(n)  asm volatile("cp.async.wait_group %0;\n" :: "n"(n))

// ---------------- graph-feature kernels ----------------
__global__ void k_zero() {
    int i = blockIdx.x * blockDim.x + threadIdx.x;
    if (i < NN * 2) { g_sumA[i] = 0.0f; g_sumB[i] = 0.0f; }
    if (i < NN)     { g_degT[i] = 0.0f; g_degH[i] = 0.0f; g_cnt[i] = 0; }
}

__global__ void k_scat1(const int* __restrict__ h_id, const int* __restrict__ t_id,
                        const float* __restrict__ topic) {
    int e = blockIdx.x * blockDim.x + threadIdx.x;
    if (e >= EE) return;
    int h = h_id[e], t = t_id[e];
    float x0 = topic[h * 2], x1 = topic[h * 2 + 1];
    atomicAdd(&g_sumA[t * 2], x0); atomicAdd(&g_sumA[t * 2 + 1], x1);
    float y0 = topic[t * 2], y1 = topic[t * 2 + 1];
    atomicAdd(&g_sumB[h * 2], y0); atomicAdd(&g_sumB[h * 2 + 1], y1);
    atomicAdd(&g_degT[t], 1.0f);
    atomicAdd(&g_degH[h], 1.0f);
    atomicAdd(&g_cnt[h], 1);      // histogram for h-sort
}

__global__ void k_build1(const float* __restrict__ ent, const float* __restrict__ nontext,
                         const float* __restrict__ topic) {
    long long idx = (long long)blockIdx.x * blockDim.x + threadIdx.x;
    if (idx >= (long long)NP * KPAD) return;
    int n = (int)(idx / KPAD), c = (int)(idx % KPAD);
    float v = 0.0f;
    if (n < NN) {
        if (c < 256) {
            v = (n < NTEXT) ? ent[(size_t)n * 256 + c] : nontext[c];
        } else if (c < 258) {
            v = topic[n * 2 + (c - 256)];
        } else if (c < 260) {
            int k = c - 258;
            v = g_sumA[n * 2 + k] / fmaxf(g_degT[n], 1.0f);
            g_sumA[n * 2 + k] = 0.0f;
        } else if (c >= 262 && c < 264) {
            int k = c - 262;
            v = g_sumB[n * 2 + k] / fmaxf(g_degH[n], 1.0f);
            g_sumB[n * 2 + k] = 0.0f;
        }
    }
    g_ext[(size_t)n * KPAD + c] = __float2half_rn(v);
}

__global__ void k_scat2(const int* __restrict__ h_id, const int* __restrict__ t_id) {
    int e = blockIdx.x * blockDim.x + threadIdx.x;
    if (e >= EE) return;
    int h = h_id[e], t = t_id[e];
    float a0 = __half2float(g_ext[(size_t)h * KPAD + 258]);
    float a1 = __half2float(g_ext[(size_t)h * KPAD + 259]);
    atomicAdd(&g_sumA[t * 2], a0); atomicAdd(&g_sumA[t * 2 + 1], a1);
    float b0 = __half2float(g_ext[(size_t)t * KPAD + 262]);
    float b1v = __half2float(g_ext[(size_t)t * KPAD + 263]);
    atomicAdd(&g_sumB[h * 2], b0); atomicAdd(&g_sumB[h * 2 + 1], b1v);
}

__global__ void k_fill2() {
    int idx = blockIdx.x * blockDim.x + threadIdx.x;
    if (idx >= NN * 2) return;
    int n = idx >> 1, k = idx & 1;
    g_ext[(size_t)n * KPAD + 260 + k] = __float2half_rn(g_sumA[n * 2 + k] / fmaxf(g_degT[n], 1.0f));
    g_ext[(size_t)n * KPAD + 264 + k] = __float2half_rn(g_sumB[n * 2 + k] / fmaxf(g_degH[n], 1.0f));
}

// ---------------- h-sort: scan + scatter ----------------
__global__ void k_scan1() {
    __shared__ int s[256];
    int b = blockIdx.x, t = threadIdx.x, i = b * 256 + t;
    int v = (i < NN) ? g_cnt[i] : 0;
    s[t] = v; __syncthreads();
#pragma unroll
    for (int o = 1; o < 256; o <<= 1) {
        int x = (t >= o) ? s[t - o] : 0;
        __syncthreads();
        s[t] += x;
        __syncthreads();
    }
    if (i < NN) g_cnt[i] = s[t] - v;     // exclusive within block
    if (t == 255) g_bsum[b] = s[t];      // block total
}

__global__ void k_scan2() {
    __shared__ int s[512];
    int t = threadIdx.x;
    int v = (t < NBSCAN) ? g_bsum[t] : 0;
    s[t] = v; __syncthreads();
#pragma unroll
    for (int o = 1; o < 512; o <<= 1) {
        int x = (t >= o) ? s[t - o] : 0;
        __syncthreads();
        s[t] += x;
        __syncthreads();
    }
    if (t < NBSCAN) g_bsum[t] = s[t] - v;  // exclusive block offsets
}

__global__ void k_scan3() {
    int b = blockIdx.x, t = threadIdx.x, i = b * 256 + t;
    if (i < NN) g_cnt[i] += g_bsum[b];
}

__global__ void k_scatter(const int* __restrict__ h_id) {
    int e = blockIdx.x * blockDim.x + threadIdx.x;
    if (e >= EE) return;
    int pos = atomicAdd(&g_cnt[h_id[e]], 1);
    g_perm[pos] = e;
}

// ---------------- weight sampling (also writes Wcat directly) ----------------
__global__ void k_sample(Keys K,
                         const float* __restrict__ w1mu, const float* __restrict__ w1rho,
                         const float* __restrict__ b1mu, const float* __restrict__ b1rho,
                         const float* __restrict__ w2mu, const float* __restrict__ w2rho,
                         const float* __restrict__ b2mu, const float* __restrict__ b2rho) {
    int i = blockIdx.y;
    int j = blockIdx.x * blockDim.x + threadIdx.x;
    unsigned int v0, v1;
    if (j < W1FLAT) {
        tf2x32(K.k[i][0][0], K.k[i][0][1], 0u, (unsigned)j, v0, v1);
        float z = bits_to_normal(v0 ^ v1);
        float val = w1mu[j] + z * softplusf(w1rho[j]);
        g_w1s[(size_t)i * W1FLAT + j] = val;
        int row = j / PREDIN, col = j - row * PREDIN;
        if (col >= 256 && col < 256 + KE) {
            g_Wcat[(size_t)(i * 512 + row) * KPAD + (col - 256)] = __float2half_rn(val);
        } else if (col >= 778) {
            g_Wcat[(size_t)(i * 512 + 256 + row) * KPAD + (col - 778)] = __float2half_rn(val);
        }
    } else if (j < W1FLAT + 256) {
        int jj = j - W1FLAT;
        tf2x32(K.k[i][1][0], K.k[i][1][1], 0u, (unsigned)jj, v0, v1);
        g_b1s[i * 256 + jj] = b1mu[jj] + bits_to_normal(v0 ^ v1) * softplusf(b1rho[jj]);
    } else if (j < W1FLAT + 512) {
        int jj = j - W1FLAT - 256;
        tf2x32(K.k[i][2][0], K.k[i][2][1], 0u, (unsigned)jj, v0, v1);
        g_w2s[i * 256 + jj] = w2mu[jj] + bits_to_normal(v0 ^ v1) * softplusf(w2rho[jj]);
    } else if (j == W1FLAT + 512) {
        tf2x32(K.k[i][3][0], K.k[i][3][1], 0u, 0u, v0, v1);
        g_b2s[i] = b2mu[0] + bits_to_normal(v0 ^ v1) * softplusf(b2rho[0]);
    }
}

__global__ void k_cvec(const float* __restrict__ q) {
    int gw = (blockIdx.x * blockDim.x + threadIdx.x) >> 5;
    int lane = threadIdx.x & 31;
    if (gw >= NSAMP * 256) return;
    int i = gw >> 8, j = gw & 255;
    const float* wrow = &g_w1s[((size_t)i * 256 + j) * PREDIN];
    float s = 0.0f;
    for (int c = lane; c < 256; c += 32) s += q[c] * wrow[c];
    for (int o = 16; o; o >>= 1) s += __shfl_down_sync(0xffffffffu, s, o);
    if (lane == 0) g_cvec[i * 256 + j] = s + g_b1s[i * 256 + j];
}

// Rc tiled GEMM: Rc[i][r][j] = rel[r] . w1[i][j][522:778] + cvec[i][j]  (fp16 out)
__global__ void __launch_bounds__(256) k_rc2(const float* __restrict__ rel) {
    __shared__ float Rs[16][68];
    __shared__ float Ws[16][68];
    int jt = blockIdx.x * 64, rt = blockIdx.y * 64, i = blockIdx.z;
    int tid = threadIdx.x;
    int lrw = tid >> 2;
    int cseg = (tid & 3) * 4;
    int tx = tid & 15, ty = tid >> 4;
    int j0 = tx * 4, r0 = ty * 4;

    float acc[4][4];
#pragma unroll
    for (int x = 0; x < 4; x++)
#pragma unroll
        for (int y = 0; y < 4; y++) acc[x][y] = 0.0f;

    for (int c0 = 0; c0 < 256; c0 += 16) {
        float4 rv = make_float4(0.f, 0.f, 0.f, 0.f);
        if (rt + lrw < NRELC)
            rv = *(const float4*)(&rel[(size_t)(rt + lrw) * 256 + c0 + cseg]);
        Rs[cseg][lrw] = rv.x; Rs[cseg + 1][lrw] = rv.y;
        Rs[cseg + 2][lrw] = rv.z; Rs[cseg + 3][lrw] = rv.w;
        const float* wp = &g_w1s[((size_t)i * 256 + jt + lrw) * PREDIN + 522 + c0 + cseg];
        float2 w0 = *(const float2*)(wp);
        float2 w1v = *(const float2*)(wp + 2);
        Ws[cseg][lrw] = w0.x; Ws[cseg + 1][lrw] = w0.y;
        Ws[cseg + 2][lrw] = w1v.x; Ws[cseg + 3][lrw] = w1v.y;
        __syncthreads();
#pragma unroll
        for (int k = 0; k < 16; k++) {
            float ra[4], wb[4];
#pragma unroll
            for (int x = 0; x < 4; x++) { ra[x] = Rs[k][r0 + x]; wb[x] = Ws[k][j0 + x]; }
#pragma unroll
            for (int x = 0; x < 4; x++)
#pragma unroll
                for (int y = 0; y < 4; y++) acc[x][y] = fmaf(ra[x], wb[y], acc[x][y]);
        }
        __syncthreads();
    }
#pragma unroll
    for (int x = 0; x < 4; x++) {
        int r = rt + r0 + x;
        if (r < NRELC) {
#pragma unroll
            for (int y = 0; y < 4; y++) {
                int j = jt + j0 + y;
                g_Rc_h[((size_t)i * NRELC + r) * 256 + j] =
                    __float2half_rn(acc[x][y] + g_cvec[i * 256 + j]);
            }
        }
    }
}

// ---------------- fp16 tensor-core GEMM, cp.async double-buffered ----------------
#define BM 128
#define BN 128
#define BK 32
#define NKITER 9
#define LDSS 40
__global__ void __launch_bounds__(256) k_gemm_f16() {
    __shared__ __half As[2][BM * LDSS];
    __shared__ __half Bs[2][BN * LDSS];
    int bm = blockIdx.y * BM, bn = blockIdx.x * BN;
    int tid = threadIdx.x;
    int wid = tid >> 5, lane = tid & 31;
    int warp_m = wid >> 2;
    int warp_n = wid & 3;
    int lr = lane >> 2;
    int lc = lane & 3;

    float acc[4][4][4];
#pragma unroll
    for (int mt = 0; mt < 4; mt++)
#pragma unroll
        for (int nt = 0; nt < 4; nt++)
#pragma unroll
            for (int c = 0; c < 4; c++) acc[mt][nt][c] = 0.0f;

    int c0 = tid;

#define LOAD_STAGE(st, k0)                                                          \
    {                                                                               \
        _Pragma("unroll")                                                           \
        for (int q = 0; q < 2; q++) {                                               \
            int c = c0 + q * 256;                                                   \
            int row = c >> 2, seg = c & 3;                                          \
            cp16(&As[st][row * LDSS + seg * 8],                                     \
                 &g_ext[(size_t)(bm + row) * KPAD + (k0) + seg * 8]);               \
            cp16(&Bs[st][row * LDSS + seg * 8],                                     \
                 &g_Wcat[(size_t)(bn + row) * KPAD + (k0) + seg * 8]);              \
        }                                                                           \
    }

    LOAD_STAGE(0, 0);
    CP_COMMIT();

    int a_lrow = lane & 15;
    int a_koff = (lane >> 4) * 8;

    for (int kb = 0; kb < NKITER; kb++) {
        CP_WAIT(0);
        __syncthreads();
        if (kb + 1 < NKITER) {
            LOAD_STAGE((kb + 1) & 1, (kb + 1) * BK);
            CP_COMMIT();
        }
        const __half* as = As[kb & 1];
        const __half* bs = Bs[kb & 1];
#pragma unroll
        for (int s = 0; s < 2; s++) {
            int kh = s * 16;
            uint32_t af[4][4];
#pragma unroll
            for (int mt = 0; mt < 4; mt++) {
                int m0 = warp_m * 64 + mt * 16;
                ldsm_x4(af[mt], &as[(m0 + a_lrow) * LDSS + kh + a_koff]);
            }
            uint32_t bf[2][4];
#pragma unroll
            for (int np = 0; np < 2; np++) {
                int n0 = warp_n * 32 + np * 16;
                ldsm_x4(bf[np], &bs[(n0 + a_lrow) * LDSS + kh + a_koff]);
            }
#pragma unroll
            for (int mt = 0; mt < 4; mt++) {
#pragma unroll
                for (int nt = 0; nt < 4; nt++) {
                    uint32_t bb[2];
                    bb[0] = bf[nt >> 1][nt & 1];
                    bb[1] = bf[nt >> 1][2 + (nt & 1)];
                    mma_f16(acc[mt][nt], af[mt], bb);
                }
            }
        }
    }

#pragma unroll
    for (int mt = 0; mt < 4; mt++) {
#pragma unroll
        for (int nt = 0; nt < 4; nt++) {
            int col = bn + warp_n * 32 + nt * 8 + lc * 2;
            int i = col >> 9;
            int jj = col & 511;
            int gr0 = bm + warp_m * 64 + mt * 16 + lr;
            int gr1 = gr0 + 8;
            __half2 v0 = __floats2half2_rn(acc[mt][nt][0], acc[mt][nt][1]);
            __half2 v1 = __floats2half2_rn(acc[mt][nt][2], acc[mt][nt][3]);
            if (jj < 256) {
                *(__half2*)(&g_A[(size_t)gr0 * NODEW + i * 256 + jj]) = v0;
                *(__half2*)(&g_A[(size_t)gr1 * NODEW + i * 256 + jj]) = v1;
            } else {
                *(__half2*)(&g_B[(size_t)gr0 * NODEW + i * 256 + jj - 256]) = v0;
                *(__half2*)(&g_B[(size_t)gr1 * NODEW + i * 256 + jj - 256]) = v1;
            }
        }
    }
}

__global__ void k_b2sum() {
    if (threadIdx.x == 0) {
        float s = 0.0f;
#pragma unroll
        for (int i = 0; i < NSAMP; i++) s += g_b2s[i];
        g_b2sum_buf[0] = s;
    }
}

// warp per edge in h-sorted order; w2 smem; Rc fp16
__global__ void __launch_bounds__(256) k_edge4(const int* __restrict__ h_id,
                                               const int* __restrict__ t_id,
                                               const int* __restrict__ r_id,
                                               float* __restrict__ out) {
    __shared__ float sw2[NSAMP * 256];
    __shared__ float sb2;
    int tid = threadIdx.x;
    for (int idx = tid; idx < NSAMP * 256; idx += 256) sw2[idx] = g_w2s[idx];
    if (tid == 0) sb2 = g_b2sum_buf[0];
    __syncthreads();

    int gw = (blockIdx.x * blockDim.x + tid) >> 5;
    int lane = tid & 31;
    if (gw >= EE) return;
    int e = g_perm[gw];
    int h = h_id[e], t = t_id[e], r = r_id[e];
    const __half* ah = &g_A[(size_t)h * NODEW];
    const __half* bt = &g_B[(size_t)t * NODEW];
    const __half* rc = &g_Rc_h[(size_t)r * 256];
    float acc = 0.0f;
#pragma unroll
    for (int i = 0; i < NSAMP; i++) {
        uint4 a4 = *(const uint4*)(ah + i * 256 + lane * 8);
        uint4 b4 = *(const uint4*)(bt + i * 256 + lane * 8);
        uint4 c4 = *(const uint4*)(rc + (size_t)i * (NRELC * 256) + lane * 8);
        const float4* w2i = (const float4*)&sw2[i * 256];
        float4 w0 = w2i[lane * 2], w1 = w2i[lane * 2 + 1];
        const __half2* a2 = (const __half2*)&a4;
        const __half2* b2 = (const __half2*)&b4;
        const __half2* c2 = (const __half2*)&c4;
#pragma unroll
        for (int p = 0; p < 4; p++) {
            float2 af = __half22float2(a2[p]);
            float2 bf = __half22float2(b2[p]);
            float2 cf = __half22float2(c2[p]);
            float wx = (p < 2) ? ((p == 0) ? w0.x : w0.z) : ((p == 2) ? w1.x : w1.z);
            float wy = (p < 2) ? ((p == 0) ? w0.y : w0.w) : ((p == 2) ? w1.y : w1.w);
            acc = fmaf(fmaxf(af.x + bf.x + cf.x, 0.0f), wx, acc);
            acc = fmaf(fmaxf(af.y + bf.y + cf.y, 0.0f), wy, acc);
        }
    }
    for (int o = 16; o; o >>= 1) acc += __shfl_down_sync(0xffffffffu, acc, o);
    if (lane == 0) out[e] = (acc + sb2) * 0.2f;
}

// ---------------- host ----------------
extern "C" void kernel_launch(void* const* d_in, const int* in_sizes, int n_in,
                              void* d_out, int out_size) {
    int sh = (n_in >= 17) ? 0 : -1;
    const int*   h_id   = (const int*)d_in[0];
    const int*   r_id   = (const int*)d_in[1];
    const int*   t_id   = (const int*)d_in[2];
    const float* q_emb  = (const float*)d_in[3];
    const float* ent    = (const float*)d_in[4];
    const float* rel    = (const float*)d_in[6 + sh];
    const float* topic  = (const float*)d_in[7 + sh];
    const float* nontxt = (const float*)d_in[8 + sh];
    const float* w1mu   = (const float*)d_in[9 + sh];
    const float* w1rho  = (const float*)d_in[10 + sh];
    const float* b1mu   = (const float*)d_in[11 + sh];
    const float* b1rho  = (const float*)d_in[12 + sh];
    const float* w2mu   = (const float*)d_in[13 + sh];
    const float* w2rho  = (const float*)d_in[14 + sh];
    const float* b2mu   = (const float*)d_in[15 + sh];
    const float* b2rho  = (const float*)d_in[16 + sh];
    float* out = (float*)d_out;

    // JAX keys (threefry_partitionable=True)
    Keys K;
    for (int i = 0; i < NSAMP; i++) {
        unsigned f0, f1;
        tf2x32(0u, 42u, 0u, (unsigned)i, f0, f1);
        for (int jj = 0; jj < 4; jj++) {
            unsigned a, b;
            tf2x32(f0, f1, 0u, (unsigned)jj, a, b);
            K.k[i][jj][0] = a; K.k[i][jj][1] = b;
        }
    }

    const int T = 256;
    // graph features + h histogram
    k_zero<<<(NN * 2 + T - 1) / T, T>>>();
    k_scat1<<<(EE + T - 1) / T, T>>>(h_id, t_id, topic);
    {
        long long tot = (long long)NP * KPAD;
        k_build1<<<(unsigned)((tot + T - 1) / T), T>>>(ent, nontxt, topic);
    }
    k_scat2<<<(EE + T - 1) / T, T>>>(h_id, t_id);
    k_fill2<<<(NN * 2 + T - 1) / T, T>>>();

    // h-sort: scan + scatter
    k_scan1<<<NBSCAN, 256>>>();
    k_scan2<<<1, 512>>>();
    k_scan3<<<NBSCAN, 256>>>();
    k_scatter<<<(EE + T - 1) / T, T>>>(h_id);

    // weight sampling (writes w1s + Wcat)
    {
        dim3 g((W1FLAT + 513 + T - 1) / T, NSAMP);
        k_sample<<<g, T>>>(K, w1mu, w1rho, b1mu, b1rho, w2mu, w2rho, b2mu, b2rho);
    }
    k_cvec<<<(NSAMP * 256 * 32 + T - 1) / T, T>>>(q_emb);
    {
        dim3 g(4, 8, NSAMP);
        k_rc2<<<g, 256>>>(rel);
    }
    k_b2sum<<<1, 32>>>();

    // big GEMM: [100096 x 288] x [2560 x 288]^T (fp16 mma.sync, cp.async pipeline)
    {
        dim3 g(CAB / BN, NP / BM);
        k_gemm_f16<<<g, 256>>>();
    }

    // edge stage: warp per edge, h-sorted
    {
        long long threads = (long long)EE * 32;
        k_edge4<<<(unsigned)((threads + T - 1) / T), T>>>(h_id, t_id, r_id, out);
    }
}

// round 17
// speedup vs baseline: 3.8749x; 1.1062x over previous
#include <cuda_runtime.h>
#include <cuda_fp16.h>
#include <cstdint>

// ---------------- problem constants ----------------
#define EE      500000
#define NN      100000
#define NP      100096   // NN padded to /128 (guard-free GEMM tiles)
#define NTEXT   90000
#define NRELC   500
#define KE      266
#define KPAD    288      // K padded to /32 (9 x BK)
#define NSAMP   5
#define PREDIN  1044
#define W1FLAT  267264   // 256*1044
#define CAB     2560
#define NODEW   1280     // per-node halves in g_A / g_B

// ---------------- device scratch (static, allowed) ----------------
__device__ __half g_ext[(size_t)NP * KPAD];
__device__ __half g_A[(size_t)NP * NODEW];
__device__ __half g_B[(size_t)NP * NODEW];
__device__ __half g_Wcat[(size_t)CAB * KPAD];   // cols >= KE stay statically zero
__device__ float g_w1s[(size_t)NSAMP * W1FLAT];
__device__ float g_b1s[NSAMP * 256];
__device__ float g_w2s[NSAMP * 256];
__device__ float g_b2s[NSAMP];
__device__ float g_cvec[NSAMP * 256];
__device__ __half g_Rc_h[(size_t)NSAMP * NRELC * 256];
__device__ float g_sumA[NN * 2];
__device__ float g_sumB[NN * 2];
__device__ float g_degT[NN];
__device__ float g_degH[NN];
__device__ float g_b2sum_buf[1];

struct Keys { unsigned int k[NSAMP][4][2]; };

// ---------------- threefry2x32 (JAX-exact) ----------------
__host__ __device__ __forceinline__ unsigned int rotl32(unsigned int x, int r) {
    return (x << r) | (x >> (32 - r));
}
__host__ __device__ __forceinline__ void tf2x32(unsigned int k0, unsigned int k1,
                                                unsigned int x0, unsigned int x1,
                                                unsigned int& o0, unsigned int& o1) {
    unsigned int ks2 = k0 ^ k1 ^ 0x1BD11BDAu;
    x0 += k0; x1 += k1;
#define TFR(r) { x0 += x1; x1 = rotl32(x1, r); x1 ^= x0; }
    TFR(13) TFR(15) TFR(26) TFR(6)   x0 += k1;  x1 += ks2 + 1u;
    TFR(17) TFR(29) TFR(16) TFR(24)  x0 += ks2; x1 += k0 + 2u;
    TFR(13) TFR(15) TFR(26) TFR(6)   x0 += k0;  x1 += k1 + 3u;
    TFR(17) TFR(29) TFR(16) TFR(24)  x0 += k1;  x1 += ks2 + 4u;
    TFR(13) TFR(15) TFR(26) TFR(6)   x0 += ks2; x1 += k0 + 5u;
#undef TFR
    o0 = x0; o1 = x1;
}

// XLA f32 ErfInv (Giles polynomial)
__device__ __forceinline__ float erfinv_f32(float x) {
    float w = -log1pf(-x * x);
    float p;
    if (w < 5.0f) {
        w -= 2.5f;
        p = 2.81022636e-08f;
        p = fmaf(p, w, 3.43273939e-07f);
        p = fmaf(p, w, -3.5233877e-06f);
        p = fmaf(p, w, -4.39150654e-06f);
        p = fmaf(p, w, 0.00021858087f);
        p = fmaf(p, w, -0.00125372503f);
        p = fmaf(p, w, -0.00417768164f);
        p = fmaf(p, w, 0.246640727f);
        p = fmaf(p, w, 1.50140941f);
    } else {
        w = sqrtf(w) - 3.0f;
        p = -0.000200214257f;
        p = fmaf(p, w, 0.000100950558f);
        p = fmaf(p, w, 0.00134934322f);
        p = fmaf(p, w, -0.00367342844f);
        p = fmaf(p, w, 0.00573950773f);
        p = fmaf(p, w, -0.0076224613f);
        p = fmaf(p, w, 0.00943887047f);
        p = fmaf(p, w, 1.00167406f);
        p = fmaf(p, w, 2.83297682f);
    }
    return p * x;
}

__device__ __forceinline__ float bits_to_normal(unsigned int b) {
    float f01 = __uint_as_float((b >> 9) | 0x3f800000u) - 1.0f;
    float u = __fadd_rn(__fmul_rn(f01, 2.0f), -0.99999994f);
    u = fmaxf(-0.99999994f, u);
    return __fmul_rn(1.41421356237f, erfinv_f32(u));
}

__device__ __forceinline__ float softplusf(float x) {
    return fmaxf(x, 0.0f) + log1pf(expf(-fabsf(x)));
}

__device__ __forceinline__ void mma_f16(float* c, const uint32_t* a, const uint32_t* b) {
    asm volatile(
        "mma.sync.aligned.m16n8k16.row.col.f32.f16.f16.f32 "
        "{%0,%1,%2,%3}, {%4,%5,%6,%7}, {%8,%9}, {%0,%1,%2,%3};\n"
        : "+f"(c[0]), "+f"(c[1]), "+f"(c[2]), "+f"(c[3])
        : "r"(a[0]), "r"(a[1]), "r"(a[2]), "r"(a[3]), "r"(b[0]), "r"(b[1]));
}

__device__ __forceinline__ void ldsm_x4(uint32_t* r, const void* sptr) {
    uint32_t a = (uint32_t)__cvta_generic_to_shared(sptr);
    asm volatile("ldmatrix.sync.aligned.m8n8.x4.shared.b16 {%0,%1,%2,%3}, [%4];"
                 : "=r"(r[0]), "=r"(r[1]), "=r"(r[2]), "=r"(r[3]) : "r"(a));
}

__device__ __forceinline__ void cp16(const void* sdst, const void* gsrc) {
    uint32_t d = (uint32_t)__cvta_generic_to_shared(sdst);
    asm volatile("cp.async.cg.shared.global [%0], [%1], 16;\n" :: "r"(d), "l"(gsrc));
}
#define CP_COMMIT() asm volatile("cp.async.commit_group;\n")
#define CP_WAIT(n)  asm volatile("cp.async.wait_group %0;\n" :: "n"(n))

// ---------------- graph-feature kernels ----------------
__global__ void k_zero() {
    int i = blockIdx.x * blockDim.x + threadIdx.x;
    if (i < NN * 2) { g_sumA[i] = 0.0f; g_sumB[i] = 0.0f; }
    if (i < NN)     { g_degT[i] = 0.0f; g_degH[i] = 0.0f; }
}

__global__ void k_scat1(const int* __restrict__ h_id, const int* __restrict__ t_id,
                        const float* __restrict__ topic) {
    int e = blockIdx.x * blockDim.x + threadIdx.x;
    if (e >= EE) return;
    int h = h_id[e], t = t_id[e];
    float x0 = topic[h * 2], x1 = topic[h * 2 + 1];
    atomicAdd(&g_sumA[t * 2], x0); atomicAdd(&g_sumA[t * 2 + 1], x1);
    float y0 = topic[t * 2], y1 = topic[t * 2 + 1];
    atomicAdd(&g_sumB[h * 2], y0); atomicAdd(&g_sumB[h * 2 + 1], y1);
    atomicAdd(&g_degT[t], 1.0f);
    atomicAdd(&g_degH[h], 1.0f);
}

__global__ void k_build1(const float* __restrict__ ent, const float* __restrict__ nontext,
                         const float* __restrict__ topic) {
    long long idx = (long long)blockIdx.x * blockDim.x + threadIdx.x;
    if (idx >= (long long)NP * KPAD) return;
    int n = (int)(idx / KPAD), c = (int)(idx % KPAD);
    float v = 0.0f;
    if (n < NN) {
        if (c < 256) {
            v = (n < NTEXT) ? ent[(size_t)n * 256 + c] : nontext[c];
        } else if (c < 258) {
            v = topic[n * 2 + (c - 256)];
        } else if (c < 260) {
            int k = c - 258;
            v = g_sumA[n * 2 + k] / fmaxf(g_degT[n], 1.0f);
            g_sumA[n * 2 + k] = 0.0f;
        } else if (c >= 262 && c < 264) {
            int k = c - 262;
            v = g_sumB[n * 2 + k] / fmaxf(g_degH[n], 1.0f);
            g_sumB[n * 2 + k] = 0.0f;
        }
    }
    g_ext[(size_t)n * KPAD + c] = __float2half_rn(v);
}

__global__ void k_scat2(const int* __restrict__ h_id, const int* __restrict__ t_id) {
    int e = blockIdx.x * blockDim.x + threadIdx.x;
    if (e >= EE) return;
    int h = h_id[e], t = t_id[e];
    float a0 = __half2float(g_ext[(size_t)h * KPAD + 258]);
    float a1 = __half2float(g_ext[(size_t)h * KPAD + 259]);
    atomicAdd(&g_sumA[t * 2], a0); atomicAdd(&g_sumA[t * 2 + 1], a1);
    float b0 = __half2float(g_ext[(size_t)t * KPAD + 262]);
    float b1v = __half2float(g_ext[(size_t)t * KPAD + 263]);
    atomicAdd(&g_sumB[h * 2], b0); atomicAdd(&g_sumB[h * 2 + 1], b1v);
}

__global__ void k_fill2() {
    int idx = blockIdx.x * blockDim.x + threadIdx.x;
    if (idx >= NN * 2) return;
    int n = idx >> 1, k = idx & 1;
    g_ext[(size_t)n * KPAD + 260 + k] = __float2half_rn(g_sumA[n * 2 + k] / fmaxf(g_degT[n], 1.0f));
    g_ext[(size_t)n * KPAD + 264 + k] = __float2half_rn(g_sumB[n * 2 + k] / fmaxf(g_degH[n], 1.0f));
}

// PARTITIONABLE threefry; also writes Wcat directly
__global__ void k_sample(Keys K,
                         const float* __restrict__ w1mu, const float* __restrict__ w1rho,
                         const float* __restrict__ b1mu, const float* __restrict__ b1rho,
                         const float* __restrict__ w2mu, const float* __restrict__ w2rho,
                         const float* __restrict__ b2mu, const float* __restrict__ b2rho) {
    int i = blockIdx.y;
    int j = blockIdx.x * blockDim.x + threadIdx.x;
    unsigned int v0, v1;
    if (j < W1FLAT) {
        tf2x32(K.k[i][0][0], K.k[i][0][1], 0u, (unsigned)j, v0, v1);
        float z = bits_to_normal(v0 ^ v1);
        float val = w1mu[j] + z * softplusf(w1rho[j]);
        g_w1s[(size_t)i * W1FLAT + j] = val;
        int row = j / PREDIN, col = j - row * PREDIN;
        if (col >= 256 && col < 256 + KE) {
            g_Wcat[(size_t)(i * 512 + row) * KPAD + (col - 256)] = __float2half_rn(val);
        } else if (col >= 778) {
            g_Wcat[(size_t)(i * 512 + 256 + row) * KPAD + (col - 778)] = __float2half_rn(val);
        }
    } else if (j < W1FLAT + 256) {
        int jj = j - W1FLAT;
        tf2x32(K.k[i][1][0], K.k[i][1][1], 0u, (unsigned)jj, v0, v1);
        g_b1s[i * 256 + jj] = b1mu[jj] + bits_to_normal(v0 ^ v1) * softplusf(b1rho[jj]);
    } else if (j < W1FLAT + 512) {
        int jj = j - W1FLAT - 256;
        tf2x32(K.k[i][2][0], K.k[i][2][1], 0u, (unsigned)jj, v0, v1);
        g_w2s[i * 256 + jj] = w2mu[jj] + bits_to_normal(v0 ^ v1) * softplusf(w2rho[jj]);
    } else if (j == W1FLAT + 512) {
        tf2x32(K.k[i][3][0], K.k[i][3][1], 0u, 0u, v0, v1);
        g_b2s[i] = b2mu[0] + bits_to_normal(v0 ^ v1) * softplusf(b2rho[0]);
    }
}

__global__ void k_cvec(const float* __restrict__ q) {
    int gw = (blockIdx.x * blockDim.x + threadIdx.x) >> 5;
    int lane = threadIdx.x & 31;
    if (gw >= NSAMP * 256) return;
    int i = gw >> 8, j = gw & 255;
    const float* wrow = &g_w1s[((size_t)i * 256 + j) * PREDIN];
    float s = 0.0f;
    for (int c = lane; c < 256; c += 32) s += q[c] * wrow[c];
    for (int o = 16; o; o >>= 1) s += __shfl_down_sync(0xffffffffu, s, o);
    if (lane == 0) g_cvec[i * 256 + j] = s + g_b1s[i * 256 + j];
}

// Rc tiled GEMM (fp16 out)
__global__ void __launch_bounds__(256) k_rc2(const float* __restrict__ rel) {
    __shared__ float Rs[16][68];
    __shared__ float Ws[16][68];
    int jt = blockIdx.x * 64, rt = blockIdx.y * 64, i = blockIdx.z;
    int tid = threadIdx.x;
    int lrw = tid >> 2;
    int cseg = (tid & 3) * 4;
    int tx = tid & 15, ty = tid >> 4;
    int j0 = tx * 4, r0 = ty * 4;

    float acc[4][4];
#pragma unroll
    for (int x = 0; x < 4; x++)
#pragma unroll
        for (int y = 0; y < 4; y++) acc[x][y] = 0.0f;

    for (int c0 = 0; c0 < 256; c0 += 16) {
        float4 rv = make_float4(0.f, 0.f, 0.f, 0.f);
        if (rt + lrw < NRELC)
            rv = *(const float4*)(&rel[(size_t)(rt + lrw) * 256 + c0 + cseg]);
        Rs[cseg][lrw] = rv.x; Rs[cseg + 1][lrw] = rv.y;
        Rs[cseg + 2][lrw] = rv.z; Rs[cseg + 3][lrw] = rv.w;
        const float* wp = &g_w1s[((size_t)i * 256 + jt + lrw) * PREDIN + 522 + c0 + cseg];
        float2 w0 = *(const float2*)(wp);
        float2 w1v = *(const float2*)(wp + 2);
        Ws[cseg][lrw] = w0.x; Ws[cseg + 1][lrw] = w0.y;
        Ws[cseg + 2][lrw] = w1v.x; Ws[cseg + 3][lrw] = w1v.y;
        __syncthreads();
#pragma unroll
        for (int k = 0; k < 16; k++) {
            float ra[4], wb[4];
#pragma unroll
            for (int x = 0; x < 4; x++) { ra[x] = Rs[k][r0 + x]; wb[x] = Ws[k][j0 + x]; }
#pragma unroll
            for (int x = 0; x < 4; x++)
#pragma unroll
                for (int y = 0; y < 4; y++) acc[x][y] = fmaf(ra[x], wb[y], acc[x][y]);
        }
        __syncthreads();
    }
#pragma unroll
    for (int x = 0; x < 4; x++) {
        int r = rt + r0 + x;
        if (r < NRELC) {
#pragma unroll
            for (int y = 0; y < 4; y++) {
                int j = jt + j0 + y;
                g_Rc_h[((size_t)i * NRELC + r) * 256 + j] =
                    __float2half_rn(acc[x][y] + g_cvec[i * 256 + j]);
            }
        }
    }
}

// ---------------- fp16 mma.sync GEMM: 4 warps, 64x64 warp tiles ----------------
// C[NP x 2560] = ext[NP x 288] * Wcat[2560 x 288]^T ; block 128x128, BK=32
#define BM 128
#define BN 128
#define BK 32
#define NKITER 9
#define LDSS 40
__global__ void __launch_bounds__(128) k_gemm_f16() {
    __shared__ __half As[2][BM * LDSS];
    __shared__ __half Bs[2][BN * LDSS];
    int bm = blockIdx.y * BM, bn = blockIdx.x * BN;
    int tid = threadIdx.x;
    int wid = tid >> 5, lane = tid & 31;
    int warp_m = wid >> 1;      // 0..1
    int warp_n = wid & 1;       // 0..1
    int lr = lane >> 2;         // 0..7
    int lc = lane & 3;          // 0..3

    float acc[4][8][4];
#pragma unroll
    for (int mt = 0; mt < 4; mt++)
#pragma unroll
        for (int nt = 0; nt < 8; nt++)
#pragma unroll
            for (int c = 0; c < 4; c++) acc[mt][nt][c] = 0.0f;

#define LOAD_STAGE(st, k0)                                                          \
    {                                                                               \
        _Pragma("unroll")                                                           \
        for (int q = 0; q < 4; q++) {                                               \
            int c = tid + q * 128;                                                  \
            int row = c >> 2, seg = c & 3;                                          \
            cp16(&As[st][row * LDSS + seg * 8],                                     \
                 &g_ext[(size_t)(bm + row) * KPAD + (k0) + seg * 8]);               \
            cp16(&Bs[st][row * LDSS + seg * 8],                                     \
                 &g_Wcat[(size_t)(bn + row) * KPAD + (k0) + seg * 8]);              \
        }                                                                           \
    }

    LOAD_STAGE(0, 0);
    CP_COMMIT();

    int a_lrow = lane & 15;
    int a_koff = (lane >> 4) * 8;

    for (int kb = 0; kb < NKITER; kb++) {
        CP_WAIT(0);
        __syncthreads();
        if (kb + 1 < NKITER) {
            LOAD_STAGE((kb + 1) & 1, (kb + 1) * BK);
            CP_COMMIT();
        }
        const __half* as = As[kb & 1];
        const __half* bs = Bs[kb & 1];
#pragma unroll
        for (int s = 0; s < 2; s++) {
            int kh = s * 16;
            uint32_t af[4][4];
#pragma unroll
            for (int mt = 0; mt < 4; mt++) {
                int m0 = warp_m * 64 + mt * 16;
                ldsm_x4(af[mt], &as[(m0 + a_lrow) * LDSS + kh + a_koff]);
            }
            uint32_t bf[4][4];
#pragma unroll
            for (int np = 0; np < 4; np++) {
                int n0 = warp_n * 64 + np * 16;
                ldsm_x4(bf[np], &bs[(n0 + a_lrow) * LDSS + kh + a_koff]);
            }
#pragma unroll
            for (int mt = 0; mt < 4; mt++) {
#pragma unroll
                for (int nt = 0; nt < 8; nt++) {
                    uint32_t bb[2];
                    bb[0] = bf[nt >> 1][nt & 1];
                    bb[1] = bf[nt >> 1][2 + (nt & 1)];
                    mma_f16(acc[mt][nt], af[mt], bb);
                }
            }
        }
    }

#pragma unroll
    for (int mt = 0; mt < 4; mt++) {
#pragma unroll
        for (int nt = 0; nt < 8; nt++) {
            int col = bn + warp_n * 64 + nt * 8 + lc * 2;
            int i = col >> 9;
            int jj = col & 511;
            int gr0 = bm + warp_m * 64 + mt * 16 + lr;
            int gr1 = gr0 + 8;
            __half2 v0 = __floats2half2_rn(acc[mt][nt][0], acc[mt][nt][1]);
            __half2 v1 = __floats2half2_rn(acc[mt][nt][2], acc[mt][nt][3]);
            if (jj < 256) {
                *(__half2*)(&g_A[(size_t)gr0 * NODEW + i * 256 + jj]) = v0;
                *(__half2*)(&g_A[(size_t)gr1 * NODEW + i * 256 + jj]) = v1;
            } else {
                *(__half2*)(&g_B[(size_t)gr0 * NODEW + i * 256 + jj - 256]) = v0;
                *(__half2*)(&g_B[(size_t)gr1 * NODEW + i * 256 + jj - 256]) = v1;
            }
        }
    }
}

__global__ void k_b2sum() {
    if (threadIdx.x == 0) {
        float s = 0.0f;
#pragma unroll
        for (int i = 0; i < NSAMP; i++) s += g_b2s[i];
        g_b2sum_buf[0] = s;
    }
}

// warp per edge; w2 smem; Rc fp16
__global__ void __launch_bounds__(256) k_edge3(const int* __restrict__ h_id,
                                               const int* __restrict__ t_id,
                                               const int* __restrict__ r_id,
                                               float* __restrict__ out) {
    __shared__ float sw2[NSAMP * 256];
    __shared__ float sb2;
    int tid = threadIdx.x;
    for (int idx = tid; idx < NSAMP * 256; idx += 256) sw2[idx] = g_w2s[idx];
    if (tid == 0) sb2 = g_b2sum_buf[0];
    __syncthreads();

    int gw = (blockIdx.x * blockDim.x + tid) >> 5;
    int lane = tid & 31;
    if (gw >= EE) return;
    int h = h_id[gw], t = t_id[gw], r = r_id[gw];
    const __half* ah = &g_A[(size_t)h * NODEW];
    const __half* bt = &g_B[(size_t)t * NODEW];
    const __half* rc = &g_Rc_h[(size_t)r * 256];
    float acc = 0.0f;
#pragma unroll
    for (int i = 0; i < NSAMP; i++) {
        uint4 a4 = *(const uint4*)(ah + i * 256 + lane * 8);
        uint4 b4 = *(const uint4*)(bt + i * 256 + lane * 8);
        uint4 c4 = *(const uint4*)(rc + (size_t)i * (NRELC * 256) + lane * 8);
        const float4* w2i = (const float4*)&sw2[i * 256];
        float4 w0 = w2i[lane * 2], w1 = w2i[lane * 2 + 1];
        const __half2* a2 = (const __half2*)&a4;
        const __half2* b2 = (const __half2*)&b4;
        const __half2* c2 = (const __half2*)&c4;
#pragma unroll
        for (int p = 0; p < 4; p++) {
            float2 af = __half22float2(a2[p]);
            float2 bf = __half22float2(b2[p]);
            float2 cf = __half22float2(c2[p]);
            float wx = (p < 2) ? ((p == 0) ? w0.x : w0.z) : ((p == 2) ? w1.x : w1.z);
            float wy = (p < 2) ? ((p == 0) ? w0.y : w0.w) : ((p == 2) ? w1.y : w1.w);
            acc = fmaf(fmaxf(af.x + bf.x + cf.x, 0.0f), wx, acc);
            acc = fmaf(fmaxf(af.y + bf.y + cf.y, 0.0f), wy, acc);
        }
    }
    for (int o = 16; o; o >>= 1) acc += __shfl_down_sync(0xffffffffu, acc, o);
    if (lane == 0) out[gw] = (acc + sb2) * 0.2f;
}

// ---------------- host ----------------
extern "C" void kernel_launch(void* const* d_in, const int* in_sizes, int n_in,
                              void* d_out, int out_size) {
    int sh = (n_in >= 17) ? 0 : -1;
    const int*   h_id   = (const int*)d_in[0];
    const int*   r_id   = (const int*)d_in[1];
    const int*   t_id   = (const int*)d_in[2];
    const float* q_emb  = (const float*)d_in[3];
    const float* ent    = (const float*)d_in[4];
    const float* rel    = (const float*)d_in[6 + sh];
    const float* topic  = (const float*)d_in[7 + sh];
    const float* nontxt = (const float*)d_in[8 + sh];
    const float* w1mu   = (const float*)d_in[9 + sh];
    const float* w1rho  = (const float*)d_in[10 + sh];
    const float* b1mu   = (const float*)d_in[11 + sh];
    const float* b1rho  = (const float*)d_in[12 + sh];
    const float* w2mu   = (const float*)d_in[13 + sh];
    const float* w2rho  = (const float*)d_in[14 + sh];
    const float* b2mu   = (const float*)d_in[15 + sh];
    const float* b2rho  = (const float*)d_in[16 + sh];
    float* out = (float*)d_out;

    // JAX keys (threefry_partitionable=True)
    Keys K;
    for (int i = 0; i < NSAMP; i++) {
        unsigned f0, f1;
        tf2x32(0u, 42u, 0u, (unsigned)i, f0, f1);
        for (int jj = 0; jj < 4; jj++) {
            unsigned a, b;
            tf2x32(f0, f1, 0u, (unsigned)jj, a, b);
            K.k[i][jj][0] = a; K.k[i][jj][1] = b;
        }
    }

    const int T = 256;
    k_zero<<<(NN * 2 + T - 1) / T, T>>>();
    k_scat1<<<(EE + T - 1) / T, T>>>(h_id, t_id, topic);
    {
        long long tot = (long long)NP * KPAD;
        k_build1<<<(unsigned)((tot + T - 1) / T), T>>>(ent, nontxt, topic);
    }
    k_scat2<<<(EE + T - 1) / T, T>>>(h_id, t_id);
    k_fill2<<<(NN * 2 + T - 1) / T, T>>>();

    {
        dim3 g((W1FLAT + 513 + T - 1) / T, NSAMP);
        k_sample<<<g, T>>>(K, w1mu, w1rho, b1mu, b1rho, w2mu, w2rho, b2mu, b2rho);
    }
    k_cvec<<<(NSAMP * 256 * 32 + T - 1) / T, T>>>(q_emb);
    {
        dim3 g(4, 8, NSAMP);
        k_rc2<<<g, 256>>>(rel);
    }
    k_b2sum<<<1, 32>>>();

    // big GEMM: [100096 x 288] x [2560 x 288]^T (fp16 mma.sync, 64x64 warp tiles)
    {
        dim3 g(CAB / BN, NP / BM);
        k_gemm_f16<<<g, 128>>>();
    }

    // edge stage
    {
        long long threads = (long long)EE * 32;
        k_edge3<<<(unsigned)((threads + T - 1) / T), T>>>(h_id, t_id, r_id, out);
    }
}